// round 8
// baseline (speedup 1.0000x reference)
#include <cuda_runtime.h>
#include <cuda_bf16.h>
#include <math.h>

#define D_MODEL 768
#define N_HEADS 12
#define HEAD_DIM 64
#define N_LAYERS 12
#define SEQ 1024
#define BATCH 4
#define ROWS (BATCH * SEQ)       // 4096
#define D_FF (4 * D_MODEL)       // 3072
#define VOCAB 50257
#define VOCAB_P 50432            // padded to multiple of 256

// ---------------- scratch (device globals; no allocation allowed) ----------------
__device__ float g_h[ROWS * D_MODEL];
__device__ float g_a[ROWS * D_MODEL];
__device__ float g_q[ROWS * D_MODEL];
__device__ float g_k[ROWS * D_MODEL];
__device__ float g_v[ROWS * D_MODEL];
__device__ float g_o[ROWS * D_MODEL];
__device__ float g_m[ROWS * D_FF];
__device__ float g_whp[D_MODEL * VOCAB_P];   // padded LM head weight

// ---------------- helpers ----------------
__device__ __forceinline__ unsigned f2tf(float x) {
    unsigned r;
    asm("cvt.rna.tf32.f32 %0, %1;" : "=r"(r) : "f"(x));
    return r;
}

__device__ __forceinline__ void mma_tf32(float* c, const unsigned* a, const unsigned* b) {
    asm volatile(
        "mma.sync.aligned.m16n8k8.row.col.f32.tf32.tf32.f32 "
        "{%0,%1,%2,%3}, {%4,%5,%6,%7}, {%8,%9}, {%0,%1,%2,%3};"
        : "+f"(c[0]), "+f"(c[1]), "+f"(c[2]), "+f"(c[3])
        : "r"(a[0]), "r"(a[1]), "r"(a[2]), "r"(a[3]), "r"(b[0]), "r"(b[1]));
}

// ---------------- embedding ----------------
__global__ void embed_kernel(const int* __restrict__ x, const float* __restrict__ wte,
                             const float* __restrict__ wpe, float* __restrict__ h) {
    int row = blockIdx.x;            // 0..4095
    int tok = x[row];
    int s = row & (SEQ - 1);
    const float* te = wte + (size_t)tok * D_MODEL;
    const float* pe = wpe + (size_t)s * D_MODEL;
    float* out = h + (size_t)row * D_MODEL;
    for (int d = threadIdx.x; d < D_MODEL; d += 256)
        out[d] = te[d] + pe[d];
}

// ---------------- pad LM head weight ----------------
__global__ void pad_wh_kernel(const float* __restrict__ Wh, float* __restrict__ WhP) {
    int row = blockIdx.y;
    int col = blockIdx.x * 256 + threadIdx.x;
    if (col < VOCAB_P)
        WhP[(size_t)row * VOCAB_P + col] =
            (col < VOCAB) ? Wh[(size_t)row * VOCAB + col] : 0.f;
}

// ---------------- layernorm (single or fused double) ----------------
template <bool DOUBLE>
__global__ void ln_kernel(const float* __restrict__ x,
                          const float* __restrict__ w1, const float* __restrict__ b1,
                          const float* __restrict__ w2, const float* __restrict__ b2,
                          float* __restrict__ y) {
    __shared__ float red[256];
    int row = blockIdx.x;
    int tid = threadIdx.x;
    const float* xr = x + (size_t)row * D_MODEL;
    float v0 = xr[tid], v1 = xr[tid + 256], v2 = xr[tid + 512];

    red[tid] = v0 + v1 + v2;
    __syncthreads();
    for (int s = 128; s > 0; s >>= 1) { if (tid < s) red[tid] += red[tid + s]; __syncthreads(); }
    float mean = red[0] * (1.0f / D_MODEL);
    __syncthreads();
    float d0 = v0 - mean, d1 = v1 - mean, d2 = v2 - mean;
    red[tid] = d0 * d0 + d1 * d1 + d2 * d2;
    __syncthreads();
    for (int s = 128; s > 0; s >>= 1) { if (tid < s) red[tid] += red[tid + s]; __syncthreads(); }
    float rstd = rsqrtf(red[0] * (1.0f / D_MODEL) + 1e-5f);
    float y0 = d0 * rstd * w1[tid]       + b1[tid];
    float y1 = d1 * rstd * w1[tid + 256] + b1[tid + 256];
    float y2 = d2 * rstd * w1[tid + 512] + b1[tid + 512];

    if (DOUBLE) {
        __syncthreads();
        red[tid] = y0 + y1 + y2;
        __syncthreads();
        for (int s = 128; s > 0; s >>= 1) { if (tid < s) red[tid] += red[tid + s]; __syncthreads(); }
        float mean2 = red[0] * (1.0f / D_MODEL);
        __syncthreads();
        float e0 = y0 - mean2, e1 = y1 - mean2, e2 = y2 - mean2;
        red[tid] = e0 * e0 + e1 * e1 + e2 * e2;
        __syncthreads();
        for (int s = 128; s > 0; s >>= 1) { if (tid < s) red[tid] += red[tid + s]; __syncthreads(); }
        float rstd2 = rsqrtf(red[0] * (1.0f / D_MODEL) + 1e-5f);
        y0 = e0 * rstd2 * w2[tid]       + b2[tid];
        y1 = e1 * rstd2 * w2[tid + 256] + b2[tid + 256];
        y2 = e2 * rstd2 * w2[tid + 512] + b2[tid + 512];
    }
    float* yr = y + (size_t)row * D_MODEL;
    yr[tid] = y0; yr[tid + 256] = y1; yr[tid + 512] = y2;
}

// ---------------- TF32 tensor-core GEMM body (128x256 tile, 512 threads) ----------------
// 16 warps, warp tile 32x64 (2 mi x 8 ni m16n8k8), software-pipelined double buffer.
// A: [M,K] fp32 row-major (M%128==0, K%16==0).
// B: fp32 row-major [K,N] (N mult of 256), or HEADED [N/64][K][64] (qkv; 4 heads/bn).
// NC: output width/stride (may be < N for padded-B); epilogue clamps col<NC.
template <bool GELU, bool RESID, bool HEADED>
__device__ __forceinline__
void gemm_body(const float* __restrict__ A, const float* __restrict__ B,
               const float* __restrict__ bias, const float* __restrict__ resid,
               float* __restrict__ C, int M, int N, int K, int NC, int bn, int bm) {
    // A fragments: [buf][mi(8)][ks(2)][lane(32)][slot(4)]
    __shared__ unsigned Asf[2][8][2][32][4];
    __shared__ unsigned Bs[2][16][264];      // k-major, 256 cols + pad
    int tid = threadIdx.x;
    int lane = tid & 31, warp = tid >> 5;
    int wmg = warp & 3;             // warp row group (4 warps along M, 32 rows each)
    int wn  = (warp >> 2) * 64;     // warp col offset (4 warps along N, 64 each)
    int lr = lane >> 2;             // 0..7
    int lc = lane & 3;              // 0..3
    int lane_s = lr * 4 + (lc ^ ((lr >> 1) & 3));   // consumer swizzled lane

    float acc[2][8][4];
#pragma unroll
    for (int mi = 0; mi < 2; mi++)
#pragma unroll
        for (int ni = 0; ni < 8; ni++)
#pragma unroll
            for (int r = 0; r < 4; r++) acc[mi][ni][r] = 0.f;

    // ---- staging indices (512 threads) ----
    int arow_l = tid >> 2;                 // 0..127
    int akc    = (tid & 3) * 4;            // 0,4,8,12
    int aks    = akc >> 3;                 // ks half
    int akb    = akc & 7;                  // 0 or 4 within half
    int aslot  = ((arow_l >> 3) & 1) + 2 * (akb >> 2);
    int ami    = arow_l >> 4;
    int alr    = arow_l & 7;
    int asw    = (alr >> 1) & 3;
    int bkr    = tid >> 5;                 // 0..15 (k row)
    int bc8    = (tid & 31) * 8;           // 0..248 (col chunk)

    const float* aptr = A + (size_t)(bm * 128 + arow_l) * K + akc;
    const float* bptr;
    int strideB;
    if (HEADED) {
        strideB = 64;
        bptr = B + ((size_t)(bn * 4 + (bc8 >> 6)) * K + bkr) * 64 + (bc8 & 63);
    } else {
        strideB = N;
        bptr = B + (size_t)bkr * N + bn * 256 + bc8;
    }

    float4 arv;
    float4 br0, br1;

    auto load_tile = [&](int k0) {
        arv = *(const float4*)(aptr + k0);
        const float* bp = bptr + (size_t)k0 * strideB;
        br0 = *(const float4*)(bp);
        br1 = *(const float4*)(bp + 4);
    };
    auto store_tile = [&](int buf) {
        unsigned* abase = &Asf[buf][ami][aks][0][0];
        abase[(alr * 4 + (0 ^ asw)) * 4 + aslot] = f2tf(arv.x);
        abase[(alr * 4 + (1 ^ asw)) * 4 + aslot] = f2tf(arv.y);
        abase[(alr * 4 + (2 ^ asw)) * 4 + aslot] = f2tf(arv.z);
        abase[(alr * 4 + (3 ^ asw)) * 4 + aslot] = f2tf(arv.w);
        uint4 p0, p1;
        p0.x = f2tf(br0.x); p0.y = f2tf(br0.y); p0.z = f2tf(br0.z); p0.w = f2tf(br0.w);
        p1.x = f2tf(br1.x); p1.y = f2tf(br1.y); p1.z = f2tf(br1.z); p1.w = f2tf(br1.w);
        *(uint4*)&Bs[buf][bkr][bc8]     = p0;
        *(uint4*)&Bs[buf][bkr][bc8 + 4] = p1;
    };

    load_tile(0);
    store_tile(0);
    __syncthreads();

    int cur = 0;
    for (int k0 = 0; k0 < K; k0 += 16) {
        bool has_next = (k0 + 16) < K;
        if (has_next) load_tile(k0 + 16);   // LDGs in flight during MMAs

#pragma unroll
        for (int ks = 0; ks < 2; ks++) {
            int kb = ks * 8;
            unsigned afr[2][4], bfr[8][2];
#pragma unroll
            for (int mi = 0; mi < 2; mi++) {
                int mig = wmg * 2 + mi;
                uint4 fa = *(const uint4*)&Asf[cur][mig][ks][lane_s][0];
                afr[mi][0] = fa.x; afr[mi][1] = fa.y;
                afr[mi][2] = fa.z; afr[mi][3] = fa.w;
            }
#pragma unroll
            for (int ni = 0; ni < 8; ni++) {
                int n0 = wn + ni * 8;
                bfr[ni][0] = Bs[cur][kb + lc][n0 + lr];
                bfr[ni][1] = Bs[cur][kb + lc + 4][n0 + lr];
            }
#pragma unroll
            for (int mi = 0; mi < 2; mi++)
#pragma unroll
                for (int ni = 0; ni < 8; ni++)
                    mma_tf32(acc[mi][ni], afr[mi], bfr[ni]);
        }

        if (has_next) store_tile(cur ^ 1);
        __syncthreads();
        cur ^= 1;
    }

    // ---- epilogue ----
#pragma unroll
    for (int mi = 0; mi < 2; mi++) {
        int row0 = bm * 128 + wmg * 32 + mi * 16 + lr;
#pragma unroll
        for (int ni = 0; ni < 8; ni++) {
            int col = bn * 256 + wn + ni * 8 + lc * 2;
#pragma unroll
            for (int half = 0; half < 2; half++) {
                int row = row0 + half * 8;
#pragma unroll
                for (int cc = 0; cc < 2; cc++) {
                    int c = col + cc;
                    if (c < NC) {
                        float val = acc[mi][ni][half * 2 + cc] + bias[c];
                        if (GELU) val = 0.5f * val * (1.0f + erff(val * 0.70710678118654752f));
                        if (RESID) val += resid[(size_t)row * NC + c];
                        C[(size_t)row * NC + c] = val;
                    }
                }
            }
        }
    }
}

template <bool GELU, bool RESID, bool HEADED>
__global__ __launch_bounds__(512, 1)
void gemm_kernel(const float* __restrict__ A, const float* __restrict__ B,
                 const float* __restrict__ bias, const float* __restrict__ resid,
                 float* __restrict__ C, int M, int N, int K, int NC) {
    gemm_body<GELU, RESID, HEADED>(A, B, bias, resid, C, M, N, K, NC,
                                   blockIdx.x, blockIdx.y);
}

// Fused Q/K/V projection: blockIdx.z selects which of the three GEMMs.
__global__ __launch_bounds__(512, 1)
void qkv_kernel(const float* __restrict__ A,
                const float* __restrict__ Wq, const float* __restrict__ Wk,
                const float* __restrict__ Wv,
                const float* __restrict__ bq, const float* __restrict__ bk,
                const float* __restrict__ bv,
                float* __restrict__ q, float* __restrict__ k, float* __restrict__ v) {
    const float* B    = (blockIdx.z == 0) ? Wq : (blockIdx.z == 1) ? Wk : Wv;
    const float* bias = (blockIdx.z == 0) ? bq : (blockIdx.z == 1) ? bk : bv;
    float*       C    = (blockIdx.z == 0) ? q  : (blockIdx.z == 1) ? k  : v;
    gemm_body<false, false, true>(A, B, bias, nullptr, C,
                                  ROWS, D_MODEL, D_MODEL, D_MODEL, blockIdx.x, blockIdx.y);
}

// ---------------- fused causal attention (flash-style, 64-row query tiles) ----------------
// Smem float4 chunks with XOR swizzle; K/V tile j+1 prefetched into registers
// while tile j computes (LDG latency hidden).
#define ATT_SMEM (3 * 1024 * 16)
__device__ __forceinline__ int chnk(int row, int e4) {
    return row * 16 + (e4 ^ ((row >> 2) & 7));
}

__global__ __launch_bounds__(256, 2)
void attn_kernel(const float* __restrict__ q, const float* __restrict__ k,
                 const float* __restrict__ v, float* __restrict__ o) {
    extern __shared__ float4 sm4[];
    float4* qs = sm4;            // 64 rows x 16 chunks
    float4* ks = sm4 + 1024;     // (reused as p)
    float4* vs = sm4 + 2048;
    int qi = blockIdx.x, hh = blockIdx.y, b = blockIdx.z;
    int tid = threadIdx.x, tx = tid & 15, ty = tid >> 4;
    const size_t base = ((size_t)b * SEQ) * D_MODEL + (size_t)hh * HEAD_DIM;
    const float inv_scale = 0.03608439182435161f;   // 1/sqrt(768)

    int str = tid >> 4;        // staging row base (x4)
    int se4 = tid & 15;        // staging chunk col

    // stage q tile (4 chunks per thread)
#pragma unroll
    for (int i = 0; i < 4; i++) {
        int r = str + 16 * i;
        qs[chnk(r, se4)] = *(const float4*)(q + base + (size_t)(qi * 64 + r) * D_MODEL + se4 * 4);
    }

    // prefetch K/V tile j=0
    float4 kr[4], vr[4];
#pragma unroll
    for (int i = 0; i < 4; i++) {
        int r = str + 16 * i;
        size_t goff = base + (size_t)r * D_MODEL + se4 * 4;
        kr[i] = *(const float4*)(k + goff);
        vr[i] = *(const float4*)(v + goff);
    }

    float m_[4], l_[4], acc[4][4];
#pragma unroll
    for (int r = 0; r < 4; r++) {
        m_[r] = -1e30f; l_[r] = 0.f;
#pragma unroll
        for (int c = 0; c < 4; c++) acc[r][c] = 0.f;
    }

    for (int j = 0; j <= qi; j++) {
        __syncthreads();   // prior PV reads done; qs staged (first iter)
#pragma unroll
        for (int i = 0; i < 4; i++) {
            int r = str + 16 * i;
            ks[chnk(r, se4)] = kr[i];
            vs[chnk(r, se4)] = vr[i];
        }
        if (j < qi) {      // prefetch next tile; latency covered by QK+softmax+PV
#pragma unroll
            for (int i = 0; i < 4; i++) {
                int r = str + 16 * i;
                size_t goff = base + (size_t)((j + 1) * 64 + r) * D_MODEL + se4 * 4;
                kr[i] = *(const float4*)(k + goff);
                vr[i] = *(const float4*)(v + goff);
            }
        }
        __syncthreads();

        float s[4][4];
#pragma unroll
        for (int r = 0; r < 4; r++)
#pragma unroll
            for (int c = 0; c < 4; c++) s[r][c] = 0.f;

#pragma unroll 4
        for (int e4 = 0; e4 < 16; e4++) {
            float4 qv[4], kv[4];
#pragma unroll
            for (int r = 0; r < 4; r++) qv[r] = qs[chnk(ty * 4 + r, e4)];
#pragma unroll
            for (int c = 0; c < 4; c++) kv[c] = ks[chnk(tx * 4 + c, e4)];
#pragma unroll
            for (int r = 0; r < 4; r++)
#pragma unroll
                for (int c = 0; c < 4; c++) {
                    s[r][c] += qv[r].x * kv[c].x;
                    s[r][c] += qv[r].y * kv[c].y;
                    s[r][c] += qv[r].z * kv[c].z;
                    s[r][c] += qv[r].w * kv[c].w;
                }
        }

#pragma unroll
        for (int r = 0; r < 4; r++)
#pragma unroll
            for (int c = 0; c < 4; c++) {
                s[r][c] *= inv_scale;
                if (j == qi && (tx * 4 + c) > (ty * 4 + r)) s[r][c] = -1e30f;
            }

#pragma unroll
        for (int r = 0; r < 4; r++) {
            float rm = fmaxf(fmaxf(s[r][0], s[r][1]), fmaxf(s[r][2], s[r][3]));
#pragma unroll
            for (int off = 1; off < 16; off <<= 1)
                rm = fmaxf(rm, __shfl_xor_sync(0xffffffffu, rm, off));
            float mnew = fmaxf(m_[r], rm);
            float alpha = __expf(m_[r] - mnew);
            float psum = 0.f;
#pragma unroll
            for (int c = 0; c < 4; c++) { float p = __expf(s[r][c] - mnew); s[r][c] = p; psum += p; }
#pragma unroll
            for (int off = 1; off < 16; off <<= 1)
                psum += __shfl_xor_sync(0xffffffffu, psum, off);
            l_[r] = l_[r] * alpha + psum;
            m_[r] = mnew;
#pragma unroll
            for (int c = 0; c < 4; c++) acc[r][c] *= alpha;
        }

        __syncthreads();   // all ks reads done -> safe to overwrite with p
#pragma unroll
        for (int r = 0; r < 4; r++)
            ks[chnk(ty * 4 + r, tx)] = make_float4(s[r][0], s[r][1], s[r][2], s[r][3]);
        __syncthreads();

#pragma unroll 4
        for (int k4 = 0; k4 < 16; k4++) {
            float4 pv[4], vv[4];
#pragma unroll
            for (int r = 0; r < 4; r++) pv[r] = ks[chnk(ty * 4 + r, k4)];
#pragma unroll
            for (int kk = 0; kk < 4; kk++) vv[kk] = vs[chnk(k4 * 4 + kk, tx)];
#pragma unroll
            for (int r = 0; r < 4; r++) {
                acc[r][0] += pv[r].x * vv[0].x; acc[r][1] += pv[r].x * vv[0].y;
                acc[r][2] += pv[r].x * vv[0].z; acc[r][3] += pv[r].x * vv[0].w;
                acc[r][0] += pv[r].y * vv[1].x; acc[r][1] += pv[r].y * vv[1].y;
                acc[r][2] += pv[r].y * vv[1].z; acc[r][3] += pv[r].y * vv[1].w;
                acc[r][0] += pv[r].z * vv[2].x; acc[r][1] += pv[r].z * vv[2].y;
                acc[r][2] += pv[r].z * vv[2].z; acc[r][3] += pv[r].z * vv[2].w;
                acc[r][0] += pv[r].w * vv[3].x; acc[r][1] += pv[r].w * vv[3].y;
                acc[r][2] += pv[r].w * vv[3].z; acc[r][3] += pv[r].w * vv[3].w;
            }
        }
    }

#pragma unroll
    for (int r = 0; r < 4; r++) {
        float invl = 1.0f / l_[r];
#pragma unroll
        for (int c = 0; c < 4; c++)
            o[base + (size_t)(qi * 64 + ty * 4 + r) * D_MODEL + tx * 4 + c] = acc[r][c] * invl;
    }
}

// ---------------- launch ----------------
extern "C" void kernel_launch(void* const* d_in, const int* in_sizes, int n_in,
                              void* d_out, int out_size) {
    const int*   x      = (const int*)  d_in[0];
    const float* wte    = (const float*)d_in[1];
    const float* wpe    = (const float*)d_in[2];
    const float* ln1_w  = (const float*)d_in[3];
    const float* ln1_b  = (const float*)d_in[4];
    const float* Wq     = (const float*)d_in[5];
    const float* bq     = (const float*)d_in[6];
    const float* Wk     = (const float*)d_in[7];
    const float* bk     = (const float*)d_in[8];
    const float* Wv     = (const float*)d_in[9];
    const float* bv     = (const float*)d_in[10];
    const float* Wp     = (const float*)d_in[11];
    const float* bp     = (const float*)d_in[12];
    const float* ln2_w  = (const float*)d_in[13];
    const float* ln2_b  = (const float*)d_in[14];
    const float* lnfc_w = (const float*)d_in[15];
    const float* lnfc_b = (const float*)d_in[16];
    const float* W1     = (const float*)d_in[17];
    const float* b1     = (const float*)d_in[18];
    const float* W2     = (const float*)d_in[19];
    const float* b2     = (const float*)d_in[20];
    const float* lnf_w  = (const float*)d_in[21];
    const float* lnf_b  = (const float*)d_in[22];
    const float* Wh     = (const float*)d_in[23];
    const float* bh     = (const float*)d_in[24];
    float* out = (float*)d_out;

    float *h, *a, *q, *k, *v, *o, *m, *whp;
    cudaGetSymbolAddress((void**)&h, g_h);
    cudaGetSymbolAddress((void**)&a, g_a);
    cudaGetSymbolAddress((void**)&q, g_q);
    cudaGetSymbolAddress((void**)&k, g_k);
    cudaGetSymbolAddress((void**)&v, g_v);
    cudaGetSymbolAddress((void**)&o, g_o);
    cudaGetSymbolAddress((void**)&m, g_m);
    cudaGetSymbolAddress((void**)&whp, g_whp);

    cudaFuncSetAttribute(attn_kernel, cudaFuncAttributeMaxDynamicSharedMemorySize, ATT_SMEM);

    embed_kernel<<<ROWS, 256>>>(x, wte, wpe, h);
    pad_wh_kernel<<<dim3((VOCAB_P + 255) / 256, D_MODEL), 256>>>(Wh, whp);

    dim3 gQKV(D_MODEL / 256, ROWS / 128, 3);          // (3, 32, 3)
    dim3 gProj(D_MODEL / 256, ROWS / 128);            // (3, 32)
    dim3 gFF1(D_FF / 256, ROWS / 128);                // (12, 32)
    dim3 gHead(VOCAB_P / 256, ROWS / 128);            // (197, 32)
    dim3 gAttn(SEQ / 64, N_HEADS, BATCH);             // (16, 12, 4)

    for (int l = 0; l < N_LAYERS; l++) {
        const float* Wq_l = Wq + (size_t)l * N_HEADS * D_MODEL * HEAD_DIM;
        const float* Wk_l = Wk + (size_t)l * N_HEADS * D_MODEL * HEAD_DIM;
        const float* Wv_l = Wv + (size_t)l * N_HEADS * D_MODEL * HEAD_DIM;
        const float* Wp_l = Wp + (size_t)l * D_MODEL * D_MODEL;
        const float* W1_l = W1 + (size_t)l * D_MODEL * D_FF;
        const float* W2_l = W2 + (size_t)l * D_FF * D_MODEL;

        ln_kernel<false><<<ROWS, 256>>>(h, ln1_w + l * D_MODEL, ln1_b + l * D_MODEL,
                                        nullptr, nullptr, a);

        qkv_kernel<<<gQKV, 512>>>(a, Wq_l, Wk_l, Wv_l,
                                  bq + l * D_MODEL, bk + l * D_MODEL, bv + l * D_MODEL,
                                  q, k, v);

        attn_kernel<<<gAttn, 256, ATT_SMEM>>>(q, k, v, o);

        gemm_kernel<false, true, false><<<gProj, 512>>>(o, Wp_l, bp + l * D_MODEL, h, h,
                                                        ROWS, D_MODEL, D_MODEL, D_MODEL);

        ln_kernel<true><<<ROWS, 256>>>(h, ln2_w + l * D_MODEL, ln2_b + l * D_MODEL,
                                       lnfc_w + l * D_MODEL, lnfc_b + l * D_MODEL, a);

        gemm_kernel<true, false, false><<<gFF1, 512>>>(a, W1_l, b1 + l * D_FF, nullptr, m,
                                                       ROWS, D_FF, D_MODEL, D_FF);
        gemm_kernel<false, true, false><<<gProj, 512>>>(m, W2_l, b2 + l * D_MODEL, h, h,
                                                        ROWS, D_MODEL, D_FF, D_MODEL);
    }

    ln_kernel<false><<<ROWS, 256>>>(h, lnf_w, lnf_b, nullptr, nullptr, a);
    gemm_kernel<false, false, false><<<gHead, 512>>>(a, whp, bh, nullptr, out,
                                                     ROWS, VOCAB_P, D_MODEL, VOCAB);
}

// round 9
// speedup vs baseline: 1.5603x; 1.5603x over previous
#include <cuda_runtime.h>
#include <cuda_bf16.h>
#include <math.h>

#define D_MODEL 768
#define N_HEADS 12
#define HEAD_DIM 64
#define N_LAYERS 12
#define SEQ 1024
#define BATCH 4
#define ROWS (BATCH * SEQ)       // 4096
#define D_FF (4 * D_MODEL)       // 3072
#define VOCAB 50257
#define VOCAB_P 50432            // padded to multiple of 256
#define WSZ (D_MODEL * D_MODEL)  // 589824

// ---------------- scratch (device globals; no allocation allowed) ----------------
__device__ float    g_h[ROWS * D_MODEL];
__device__ unsigned g_a[ROWS * D_MODEL];     // tf32 activations (LN out)
__device__ float    g_q[ROWS * D_MODEL];
__device__ float    g_k[ROWS * D_MODEL];
__device__ float    g_v[ROWS * D_MODEL];
__device__ unsigned g_o[ROWS * D_MODEL];     // tf32 attn out
__device__ unsigned g_m[ROWS * D_FF];        // tf32 FF1 out
// tf32 pre-converted weights
__device__ unsigned g_wq[N_LAYERS * WSZ];
__device__ unsigned g_wk[N_LAYERS * WSZ];
__device__ unsigned g_wv[N_LAYERS * WSZ];
__device__ unsigned g_wp[N_LAYERS * WSZ];
__device__ unsigned g_w1[N_LAYERS * WSZ * 4];
__device__ unsigned g_w2[N_LAYERS * WSZ * 4];
__device__ unsigned g_whp[D_MODEL * VOCAB_P];

// ---------------- helpers ----------------
__device__ __forceinline__ unsigned f2tf(float x) {
    unsigned r;
    asm("cvt.rna.tf32.f32 %0, %1;" : "=r"(r) : "f"(x));
    return r;
}

__device__ __forceinline__ void mma_tf32(float* c, const unsigned* a, const unsigned* b) {
    asm volatile(
        "mma.sync.aligned.m16n8k8.row.col.f32.tf32.tf32.f32 "
        "{%0,%1,%2,%3}, {%4,%5,%6,%7}, {%8,%9}, {%0,%1,%2,%3};"
        : "+f"(c[0]), "+f"(c[1]), "+f"(c[2]), "+f"(c[3])
        : "r"(a[0]), "r"(a[1]), "r"(a[2]), "r"(a[3]), "r"(b[0]), "r"(b[1]));
}

__device__ __forceinline__ void cp16(unsigned saddr, const unsigned* gptr) {
    asm volatile("cp.async.cg.shared.global [%0], [%1], 16;"
                 :: "r"(saddr), "l"(gptr) : "memory");
}

// ---------------- weight conversion (fp32 -> tf32 bits), vectorized ----------------
__global__ void cvt_kernel(const float* __restrict__ src, unsigned* __restrict__ dst, int n4) {
    int i = blockIdx.x * 256 + threadIdx.x;
    if (i < n4) {
        float4 v = ((const float4*)src)[i];
        uint4 u;
        u.x = f2tf(v.x); u.y = f2tf(v.y); u.z = f2tf(v.z); u.w = f2tf(v.w);
        ((uint4*)dst)[i] = u;
    }
}

// ---------------- pad + convert LM head weight ----------------
__global__ void pad_wh_kernel(const float* __restrict__ Wh, unsigned* __restrict__ WhP) {
    int row = blockIdx.y;
    int col = blockIdx.x * 256 + threadIdx.x;
    if (col < VOCAB_P)
        WhP[(size_t)row * VOCAB_P + col] =
            (col < VOCAB) ? f2tf(Wh[(size_t)row * VOCAB + col]) : 0u;
}

// ---------------- embedding ----------------
__global__ void embed_kernel(const int* __restrict__ x, const float* __restrict__ wte,
                             const float* __restrict__ wpe, float* __restrict__ h) {
    int row = blockIdx.x;            // 0..4095
    int tok = x[row];
    int s = row & (SEQ - 1);
    const float* te = wte + (size_t)tok * D_MODEL;
    const float* pe = wpe + (size_t)s * D_MODEL;
    float* out = h + (size_t)row * D_MODEL;
    for (int d = threadIdx.x; d < D_MODEL; d += 256)
        out[d] = te[d] + pe[d];
}

// ---------------- layernorm (single or fused double), tf32 output ----------------
template <bool DOUBLE>
__global__ void ln_kernel(const float* __restrict__ x,
                          const float* __restrict__ w1, const float* __restrict__ b1,
                          const float* __restrict__ w2, const float* __restrict__ b2,
                          unsigned* __restrict__ y) {
    __shared__ float red[256];
    int row = blockIdx.x;
    int tid = threadIdx.x;
    const float* xr = x + (size_t)row * D_MODEL;
    float v0 = xr[tid], v1 = xr[tid + 256], v2 = xr[tid + 512];

    red[tid] = v0 + v1 + v2;
    __syncthreads();
    for (int s = 128; s > 0; s >>= 1) { if (tid < s) red[tid] += red[tid + s]; __syncthreads(); }
    float mean = red[0] * (1.0f / D_MODEL);
    __syncthreads();
    float d0 = v0 - mean, d1 = v1 - mean, d2 = v2 - mean;
    red[tid] = d0 * d0 + d1 * d1 + d2 * d2;
    __syncthreads();
    for (int s = 128; s > 0; s >>= 1) { if (tid < s) red[tid] += red[tid + s]; __syncthreads(); }
    float rstd = rsqrtf(red[0] * (1.0f / D_MODEL) + 1e-5f);
    float y0 = d0 * rstd * w1[tid]       + b1[tid];
    float y1 = d1 * rstd * w1[tid + 256] + b1[tid + 256];
    float y2 = d2 * rstd * w1[tid + 512] + b1[tid + 512];

    if (DOUBLE) {
        __syncthreads();
        red[tid] = y0 + y1 + y2;
        __syncthreads();
        for (int s = 128; s > 0; s >>= 1) { if (tid < s) red[tid] += red[tid + s]; __syncthreads(); }
        float mean2 = red[0] * (1.0f / D_MODEL);
        __syncthreads();
        float e0 = y0 - mean2, e1 = y1 - mean2, e2 = y2 - mean2;
        red[tid] = e0 * e0 + e1 * e1 + e2 * e2;
        __syncthreads();
        for (int s = 128; s > 0; s >>= 1) { if (tid < s) red[tid] += red[tid + s]; __syncthreads(); }
        float rstd2 = rsqrtf(red[0] * (1.0f / D_MODEL) + 1e-5f);
        y0 = e0 * rstd2 * w2[tid]       + b2[tid];
        y1 = e1 * rstd2 * w2[tid + 256] + b2[tid + 256];
        y2 = e2 * rstd2 * w2[tid + 512] + b2[tid + 512];
    }
    unsigned* yr = y + (size_t)row * D_MODEL;
    yr[tid] = f2tf(y0); yr[tid + 256] = f2tf(y1); yr[tid + 512] = f2tf(y2);
}

// ---------------- TF32 tensor-core GEMM body (128x256 tile, 256 threads) ----------------
// 8 warps, warp tile 64x64 (4 mi x 8 ni m16n8k8), double-buffered; B staged by cp.async,
// A staged by LDG.128 + scatter STS (both operands pre-converted tf32 bits).
// A: [M,K] tf32 bits (M%128==0, K%16==0).
// B: tf32 bits [K,N] (N mult of 256), or HEADED [N/64][K][64] (qkv; 4 heads/bn).
// NC: output width/stride; epilogue clamps col<NC. OUTTF: store f2tf bits.
template <bool GELU, bool RESID, bool HEADED, bool OUTTF>
__device__ __forceinline__
void gemm_body(const unsigned* __restrict__ A, const unsigned* __restrict__ B,
               const float* __restrict__ bias, const float* __restrict__ resid,
               void* __restrict__ Cv, int M, int N, int K, int NC, int bn, int bm) {
    __shared__ unsigned Asf[2][8][2][32][4];   // fragment-order A
    __shared__ unsigned Bs[2][16][264];        // k-major B, 256 cols + pad
    int tid = threadIdx.x;
    int lane = tid & 31, warp = tid >> 5;
    int wm = (warp & 1) * 64;       // 2 warps along M
    int wn = (warp >> 1) * 64;      // 4 warps along N
    int lr = lane >> 2;
    int lc = lane & 3;
    int lane_s = lr * 4 + (lc ^ ((lr >> 1) & 3));

    float acc[4][8][4];
#pragma unroll
    for (int mi = 0; mi < 4; mi++)
#pragma unroll
        for (int ni = 0; ni < 8; ni++)
#pragma unroll
            for (int r = 0; r < 4; r++) acc[mi][ni][r] = 0.f;

    // staging indices
    int arow_l = tid >> 1;                 // 0..127
    int akc0   = (tid & 1) * 8;            // 0 or 8
    int aks    = tid & 1;
    int ami    = arow_l >> 4;
    int alr    = arow_l & 7;
    int ahi    = (arow_l >> 3) & 1;
    int asw    = (alr >> 1) & 3;
    int bkr    = tid >> 4;                 // 0..15
    int bcl    = (tid & 15) * 4;           // 0..60

    const unsigned* aptr = A + (size_t)(bm * 128 + arow_l) * K + akc0;
    const unsigned* bptr[4];
    int strideB;
    if (HEADED) {
        strideB = 64;
#pragma unroll
        for (int c = 0; c < 4; c++)
            bptr[c] = B + ((size_t)(bn * 4 + c) * K + bkr) * 64 + bcl;
    } else {
        strideB = N;
#pragma unroll
        for (int c = 0; c < 4; c++)
            bptr[c] = B + (size_t)bkr * N + bn * 256 + c * 64 + bcl;
    }
    unsigned bsaddr[2][4];
#pragma unroll
    for (int buf = 0; buf < 2; buf++)
#pragma unroll
        for (int c = 0; c < 4; c++)
            bsaddr[buf][c] = (unsigned)__cvta_generic_to_shared(&Bs[buf][bkr][c * 64 + bcl]);

    uint4 a0, a1;
    auto loadA = [&](int k0) {
        a0 = *(const uint4*)(aptr + k0);
        a1 = *(const uint4*)(aptr + k0 + 4);
    };
    auto storeA = [&](int buf) {
        unsigned* abase = &Asf[buf][ami][aks][0][0];
        unsigned ar[8] = {a0.x, a0.y, a0.z, a0.w, a1.x, a1.y, a1.z, a1.w};
#pragma unroll
        for (int j = 0; j < 8; j++) {
            int ls   = alr * 4 + ((j & 3) ^ asw);
            int slot = ahi + 2 * (j >> 2);
            abase[ls * 4 + slot] = ar[j];
        }
    };
    auto stageB = [&](int k0, int buf) {
#pragma unroll
        for (int c = 0; c < 4; c++)
            cp16(bsaddr[buf][c], bptr[c] + (size_t)k0 * strideB);
        asm volatile("cp.async.commit_group;" ::: "memory");
    };

    stageB(0, 0);
    loadA(0);
    storeA(0);
    asm volatile("cp.async.wait_all;" ::: "memory");
    __syncthreads();

    int cur = 0;
    for (int k0 = 0; k0 < K; k0 += 16) {
        bool has_next = (k0 + 16) < K;
        if (has_next) {
            stageB(k0 + 16, cur ^ 1);   // async G->S in flight during MMAs
            loadA(k0 + 16);             // LDGs in flight during MMAs
        }

#pragma unroll
        for (int ks = 0; ks < 2; ks++) {
            int kb = ks * 8;
            unsigned afr[4][4], bfr[8][2];
#pragma unroll
            for (int mi = 0; mi < 4; mi++) {
                int mig = (warp & 1) * 4 + mi;
                uint4 fa = *(const uint4*)&Asf[cur][mig][ks][lane_s][0];
                afr[mi][0] = fa.x; afr[mi][1] = fa.y;
                afr[mi][2] = fa.z; afr[mi][3] = fa.w;
            }
#pragma unroll
            for (int ni = 0; ni < 8; ni++) {
                int n0 = wn + ni * 8;
                bfr[ni][0] = Bs[cur][kb + lc][n0 + lr];
                bfr[ni][1] = Bs[cur][kb + lc + 4][n0 + lr];
            }
#pragma unroll
            for (int mi = 0; mi < 4; mi++)
#pragma unroll
                for (int ni = 0; ni < 8; ni++)
                    mma_tf32(acc[mi][ni], afr[mi], bfr[ni]);
        }

        if (has_next) storeA(cur ^ 1);
        asm volatile("cp.async.wait_all;" ::: "memory");
        __syncthreads();
        cur ^= 1;
    }

    // ---- epilogue ----
    float*    Cf = (float*)Cv;
    unsigned* Cu = (unsigned*)Cv;
#pragma unroll
    for (int mi = 0; mi < 4; mi++) {
        int row0 = bm * 128 + wm + mi * 16 + lr;
#pragma unroll
        for (int ni = 0; ni < 8; ni++) {
            int col = bn * 256 + wn + ni * 8 + lc * 2;
#pragma unroll
            for (int half = 0; half < 2; half++) {
                int row = row0 + half * 8;
#pragma unroll
                for (int cc = 0; cc < 2; cc++) {
                    int c = col + cc;
                    if (c < NC) {
                        float val = acc[mi][ni][half * 2 + cc] + bias[c];
                        if (GELU) val = 0.5f * val * (1.0f + erff(val * 0.70710678118654752f));
                        if (RESID) val += resid[(size_t)row * NC + c];
                        if (OUTTF) Cu[(size_t)row * NC + c] = f2tf(val);
                        else       Cf[(size_t)row * NC + c] = val;
                    }
                }
            }
        }
    }
}

template <bool GELU, bool RESID, bool HEADED, bool OUTTF>
__global__ __launch_bounds__(256, 1)
void gemm_kernel(const unsigned* __restrict__ A, const unsigned* __restrict__ B,
                 const float* __restrict__ bias, const float* __restrict__ resid,
                 void* __restrict__ C, int M, int N, int K, int NC) {
    gemm_body<GELU, RESID, HEADED, OUTTF>(A, B, bias, resid, C, M, N, K, NC,
                                          blockIdx.x, blockIdx.y);
}

// Fused Q/K/V projection: blockIdx.z selects which of the three GEMMs.
__global__ __launch_bounds__(256, 1)
void qkv_kernel(const unsigned* __restrict__ A,
                const unsigned* __restrict__ Wq, const unsigned* __restrict__ Wk,
                const unsigned* __restrict__ Wv,
                const float* __restrict__ bq, const float* __restrict__ bk,
                const float* __restrict__ bv,
                float* __restrict__ q, float* __restrict__ k, float* __restrict__ v) {
    const unsigned* B  = (blockIdx.z == 0) ? Wq : (blockIdx.z == 1) ? Wk : Wv;
    const float* bias  = (blockIdx.z == 0) ? bq : (blockIdx.z == 1) ? bk : bv;
    float*       C     = (blockIdx.z == 0) ? q  : (blockIdx.z == 1) ? k  : v;
    gemm_body<false, false, true, false>(A, B, bias, nullptr, C,
                                         ROWS, D_MODEL, D_MODEL, D_MODEL,
                                         blockIdx.x, blockIdx.y);
}

// ---------------- fused causal attention (flash-style, 64-row query tiles) ----------------
#define ATT_SMEM (3 * 1024 * 16)
__device__ __forceinline__ int chnk(int row, int e4) {
    return row * 16 + (e4 ^ ((row >> 2) & 7));
}

__global__ __launch_bounds__(256, 2)
void attn_kernel(const float* __restrict__ q, const float* __restrict__ k,
                 const float* __restrict__ v, unsigned* __restrict__ o) {
    extern __shared__ float4 sm4[];
    float4* qs = sm4;            // 64 rows x 16 chunks
    float4* ks = sm4 + 1024;     // (reused as p)
    float4* vs = sm4 + 2048;
    int qi = blockIdx.x, hh = blockIdx.y, b = blockIdx.z;
    int tid = threadIdx.x, tx = tid & 15, ty = tid >> 4;
    const size_t base = ((size_t)b * SEQ) * D_MODEL + (size_t)hh * HEAD_DIM;
    const float inv_scale = 0.03608439182435161f;   // 1/sqrt(768)

    int str = tid >> 4;
    int se4 = tid & 15;

#pragma unroll
    for (int i = 0; i < 4; i++) {
        int r = str + 16 * i;
        qs[chnk(r, se4)] = *(const float4*)(q + base + (size_t)(qi * 64 + r) * D_MODEL + se4 * 4);
    }

    float4 kr[4], vr[4];
#pragma unroll
    for (int i = 0; i < 4; i++) {
        int r = str + 16 * i;
        size_t goff = base + (size_t)r * D_MODEL + se4 * 4;
        kr[i] = *(const float4*)(k + goff);
        vr[i] = *(const float4*)(v + goff);
    }

    float m_[4], l_[4], acc[4][4];
#pragma unroll
    for (int r = 0; r < 4; r++) {
        m_[r] = -1e30f; l_[r] = 0.f;
#pragma unroll
        for (int c = 0; c < 4; c++) acc[r][c] = 0.f;
    }

    for (int j = 0; j <= qi; j++) {
        __syncthreads();
#pragma unroll
        for (int i = 0; i < 4; i++) {
            int r = str + 16 * i;
            ks[chnk(r, se4)] = kr[i];
            vs[chnk(r, se4)] = vr[i];
        }
        if (j < qi) {
#pragma unroll
            for (int i = 0; i < 4; i++) {
                int r = str + 16 * i;
                size_t goff = base + (size_t)((j + 1) * 64 + r) * D_MODEL + se4 * 4;
                kr[i] = *(const float4*)(k + goff);
                vr[i] = *(const float4*)(v + goff);
            }
        }
        __syncthreads();

        float s[4][4];
#pragma unroll
        for (int r = 0; r < 4; r++)
#pragma unroll
            for (int c = 0; c < 4; c++) s[r][c] = 0.f;

#pragma unroll 4
        for (int e4 = 0; e4 < 16; e4++) {
            float4 qv[4], kv[4];
#pragma unroll
            for (int r = 0; r < 4; r++) qv[r] = qs[chnk(ty * 4 + r, e4)];
#pragma unroll
            for (int c = 0; c < 4; c++) kv[c] = ks[chnk(tx * 4 + c, e4)];
#pragma unroll
            for (int r = 0; r < 4; r++)
#pragma unroll
                for (int c = 0; c < 4; c++) {
                    s[r][c] += qv[r].x * kv[c].x;
                    s[r][c] += qv[r].y * kv[c].y;
                    s[r][c] += qv[r].z * kv[c].z;
                    s[r][c] += qv[r].w * kv[c].w;
                }
        }

#pragma unroll
        for (int r = 0; r < 4; r++)
#pragma unroll
            for (int c = 0; c < 4; c++) {
                s[r][c] *= inv_scale;
                if (j == qi && (tx * 4 + c) > (ty * 4 + r)) s[r][c] = -1e30f;
            }

#pragma unroll
        for (int r = 0; r < 4; r++) {
            float rm = fmaxf(fmaxf(s[r][0], s[r][1]), fmaxf(s[r][2], s[r][3]));
#pragma unroll
            for (int off = 1; off < 16; off <<= 1)
                rm = fmaxf(rm, __shfl_xor_sync(0xffffffffu, rm, off));
            float mnew = fmaxf(m_[r], rm);
            float alpha = __expf(m_[r] - mnew);
            float psum = 0.f;
#pragma unroll
            for (int c = 0; c < 4; c++) { float p = __expf(s[r][c] - mnew); s[r][c] = p; psum += p; }
#pragma unroll
            for (int off = 1; off < 16; off <<= 1)
                psum += __shfl_xor_sync(0xffffffffu, psum, off);
            l_[r] = l_[r] * alpha + psum;
            m_[r] = mnew;
#pragma unroll
            for (int c = 0; c < 4; c++) acc[r][c] *= alpha;
        }

        __syncthreads();
#pragma unroll
        for (int r = 0; r < 4; r++)
            ks[chnk(ty * 4 + r, tx)] = make_float4(s[r][0], s[r][1], s[r][2], s[r][3]);
        __syncthreads();

#pragma unroll 4
        for (int k4 = 0; k4 < 16; k4++) {
            float4 pv[4], vv[4];
#pragma unroll
            for (int r = 0; r < 4; r++) pv[r] = ks[chnk(ty * 4 + r, k4)];
#pragma unroll
            for (int kk = 0; kk < 4; kk++) vv[kk] = vs[chnk(k4 * 4 + kk, tx)];
#pragma unroll
            for (int r = 0; r < 4; r++) {
                acc[r][0] += pv[r].x * vv[0].x; acc[r][1] += pv[r].x * vv[0].y;
                acc[r][2] += pv[r].x * vv[0].z; acc[r][3] += pv[r].x * vv[0].w;
                acc[r][0] += pv[r].y * vv[1].x; acc[r][1] += pv[r].y * vv[1].y;
                acc[r][2] += pv[r].y * vv[1].z; acc[r][3] += pv[r].y * vv[1].w;
                acc[r][0] += pv[r].z * vv[2].x; acc[r][1] += pv[r].z * vv[2].y;
                acc[r][2] += pv[r].z * vv[2].z; acc[r][3] += pv[r].z * vv[2].w;
                acc[r][0] += pv[r].w * vv[3].x; acc[r][1] += pv[r].w * vv[3].y;
                acc[r][2] += pv[r].w * vv[3].z; acc[r][3] += pv[r].w * vv[3].w;
            }
        }
    }

#pragma unroll
    for (int r = 0; r < 4; r++) {
        float invl = 1.0f / l_[r];
#pragma unroll
        for (int c = 0; c < 4; c++)
            o[base + (size_t)(qi * 64 + ty * 4 + r) * D_MODEL + tx * 4 + c] =
                f2tf(acc[r][c] * invl);
    }
}

// ---------------- launch ----------------
extern "C" void kernel_launch(void* const* d_in, const int* in_sizes, int n_in,
                              void* d_out, int out_size) {
    const int*   x      = (const int*)  d_in[0];
    const float* wte    = (const float*)d_in[1];
    const float* wpe    = (const float*)d_in[2];
    const float* ln1_w  = (const float*)d_in[3];
    const float* ln1_b  = (const float*)d_in[4];
    const float* Wq     = (const float*)d_in[5];
    const float* bq     = (const float*)d_in[6];
    const float* Wk     = (const float*)d_in[7];
    const float* bk     = (const float*)d_in[8];
    const float* Wv     = (const float*)d_in[9];
    const float* bv     = (const float*)d_in[10];
    const float* Wp     = (const float*)d_in[11];
    const float* bp     = (const float*)d_in[12];
    const float* ln2_w  = (const float*)d_in[13];
    const float* ln2_b  = (const float*)d_in[14];
    const float* lnfc_w = (const float*)d_in[15];
    const float* lnfc_b = (const float*)d_in[16];
    const float* W1     = (const float*)d_in[17];
    const float* b1     = (const float*)d_in[18];
    const float* W2     = (const float*)d_in[19];
    const float* b2     = (const float*)d_in[20];
    const float* lnf_w  = (const float*)d_in[21];
    const float* lnf_b  = (const float*)d_in[22];
    const float* Wh     = (const float*)d_in[23];
    const float* bh     = (const float*)d_in[24];
    float* out = (float*)d_out;

    float *h, *q, *k, *v;
    unsigned *a, *o, *m, *whp, *wq, *wk, *wv, *wp, *w1, *w2;
    cudaGetSymbolAddress((void**)&h, g_h);
    cudaGetSymbolAddress((void**)&a, g_a);
    cudaGetSymbolAddress((void**)&q, g_q);
    cudaGetSymbolAddress((void**)&k, g_k);
    cudaGetSymbolAddress((void**)&v, g_v);
    cudaGetSymbolAddress((void**)&o, g_o);
    cudaGetSymbolAddress((void**)&m, g_m);
    cudaGetSymbolAddress((void**)&whp, g_whp);
    cudaGetSymbolAddress((void**)&wq, g_wq);
    cudaGetSymbolAddress((void**)&wk, g_wk);
    cudaGetSymbolAddress((void**)&wv, g_wv);
    cudaGetSymbolAddress((void**)&wp, g_wp);
    cudaGetSymbolAddress((void**)&w1, g_w1);
    cudaGetSymbolAddress((void**)&w2, g_w2);

    cudaFuncSetAttribute(attn_kernel, cudaFuncAttributeMaxDynamicSharedMemorySize, ATT_SMEM);

    // one-time conversions (inside the graph; ~150us total)
    int nW  = N_LAYERS * WSZ / 4;       // float4 count
    int nW4 = N_LAYERS * WSZ;           // = 4*D*D*L/4 for W1/W2
    cvt_kernel<<<(nW + 255) / 256, 256>>>(Wq, wq, nW);
    cvt_kernel<<<(nW + 255) / 256, 256>>>(Wk, wk, nW);
    cvt_kernel<<<(nW + 255) / 256, 256>>>(Wv, wv, nW);
    cvt_kernel<<<(nW + 255) / 256, 256>>>(Wp, wp, nW);
    cvt_kernel<<<(nW4 + 255) / 256, 256>>>(W1, w1, nW4);
    cvt_kernel<<<(nW4 + 255) / 256, 256>>>(W2, w2, nW4);
    pad_wh_kernel<<<dim3((VOCAB_P + 255) / 256, D_MODEL), 256>>>(Wh, whp);

    embed_kernel<<<ROWS, 256>>>(x, wte, wpe, h);

    dim3 gQKV(D_MODEL / 256, ROWS / 128, 3);          // (3, 32, 3)
    dim3 gProj(D_MODEL / 256, ROWS / 128);            // (3, 32)
    dim3 gFF1(D_FF / 256, ROWS / 128);                // (12, 32)
    dim3 gHead(VOCAB_P / 256, ROWS / 128);            // (197, 32)
    dim3 gAttn(SEQ / 64, N_HEADS, BATCH);             // (16, 12, 4)

    for (int l = 0; l < N_LAYERS; l++) {
        const unsigned* wq_l = wq + (size_t)l * WSZ;
        const unsigned* wk_l = wk + (size_t)l * WSZ;
        const unsigned* wv_l = wv + (size_t)l * WSZ;
        const unsigned* wp_l = wp + (size_t)l * WSZ;
        const unsigned* w1_l = w1 + (size_t)l * WSZ * 4;
        const unsigned* w2_l = w2 + (size_t)l * WSZ * 4;

        ln_kernel<false><<<ROWS, 256>>>(h, ln1_w + l * D_MODEL, ln1_b + l * D_MODEL,
                                        nullptr, nullptr, a);

        qkv_kernel<<<gQKV, 256>>>(a, wq_l, wk_l, wv_l,
                                  bq + l * D_MODEL, bk + l * D_MODEL, bv + l * D_MODEL,
                                  q, k, v);

        attn_kernel<<<gAttn, 256, ATT_SMEM>>>(q, k, v, o);

        gemm_kernel<false, true, false, false><<<gProj, 256>>>(o, wp_l, bp + l * D_MODEL, h, h,
                                                               ROWS, D_MODEL, D_MODEL, D_MODEL);

        ln_kernel<true><<<ROWS, 256>>>(h, ln2_w + l * D_MODEL, ln2_b + l * D_MODEL,
                                       lnfc_w + l * D_MODEL, lnfc_b + l * D_MODEL, a);

        gemm_kernel<true, false, false, true><<<gFF1, 256>>>(a, w1_l, b1 + l * D_FF, nullptr, m,
                                                             ROWS, D_FF, D_MODEL, D_FF);
        gemm_kernel<false, true, false, false><<<gProj, 256>>>(m, w2_l, b2 + l * D_MODEL, h, h,
                                                               ROWS, D_MODEL, D_FF, D_MODEL);
    }

    ln_kernel<false><<<ROWS, 256>>>(h, lnf_w, lnf_b, nullptr, nullptr, a);
    gemm_kernel<false, false, false, false><<<gHead, 256>>>(a, whp, bh, nullptr, out,
                                                            ROWS, VOCAB_P, D_MODEL, VOCAB);
}

// round 10
// speedup vs baseline: 1.8019x; 1.1549x over previous
#include <cuda_runtime.h>
#include <cuda_bf16.h>
#include <math.h>

#define D_MODEL 768
#define N_HEADS 12
#define HEAD_DIM 64
#define N_LAYERS 12
#define SEQ 1024
#define BATCH 4
#define ROWS (BATCH * SEQ)       // 4096
#define D_FF (4 * D_MODEL)       // 3072
#define VOCAB 50257
#define VOCAB_P 50432            // padded to multiple of 256
#define WSZ (D_MODEL * D_MODEL)  // 589824

// ---------------- scratch (device globals; no allocation allowed) ----------------
__device__ float    g_h[ROWS * D_MODEL];
__device__ unsigned g_a[ROWS * D_MODEL];     // tf32 activations (LN out)
__device__ unsigned g_q[ROWS * D_MODEL];     // tf32 q
__device__ unsigned g_k[ROWS * D_MODEL];     // tf32 k
__device__ unsigned g_v[ROWS * D_MODEL];     // tf32 v
__device__ unsigned g_o[ROWS * D_MODEL];     // tf32 attn out
__device__ unsigned g_m[ROWS * D_FF];        // tf32 FF1 out
// tf32 pre-converted weights
__device__ unsigned g_wq[N_LAYERS * WSZ];
__device__ unsigned g_wk[N_LAYERS * WSZ];
__device__ unsigned g_wv[N_LAYERS * WSZ];
__device__ unsigned g_wp[N_LAYERS * WSZ];
__device__ unsigned g_w1[N_LAYERS * WSZ * 4];
__device__ unsigned g_w2[N_LAYERS * WSZ * 4];
__device__ unsigned g_whp[D_MODEL * VOCAB_P];

// ---------------- helpers ----------------
__device__ __forceinline__ unsigned f2tf(float x) {
    unsigned r;
    asm("cvt.rna.tf32.f32 %0, %1;" : "=r"(r) : "f"(x));
    return r;
}

__device__ __forceinline__ void mma_tf32(float* c, const unsigned* a, const unsigned* b) {
    asm volatile(
        "mma.sync.aligned.m16n8k8.row.col.f32.tf32.tf32.f32 "
        "{%0,%1,%2,%3}, {%4,%5,%6,%7}, {%8,%9}, {%0,%1,%2,%3};"
        : "+f"(c[0]), "+f"(c[1]), "+f"(c[2]), "+f"(c[3])
        : "r"(a[0]), "r"(a[1]), "r"(a[2]), "r"(a[3]), "r"(b[0]), "r"(b[1]));
}

__device__ __forceinline__ void cp16(unsigned saddr, const unsigned* gptr) {
    asm volatile("cp.async.cg.shared.global [%0], [%1], 16;"
                 :: "r"(saddr), "l"(gptr) : "memory");
}

// ---------------- weight conversion (fp32 -> tf32 bits), vectorized ----------------
__global__ void cvt_kernel(const float* __restrict__ src, unsigned* __restrict__ dst, int n4) {
    int i = blockIdx.x * 256 + threadIdx.x;
    if (i < n4) {
        float4 v = ((const float4*)src)[i];
        uint4 u;
        u.x = f2tf(v.x); u.y = f2tf(v.y); u.z = f2tf(v.z); u.w = f2tf(v.w);
        ((uint4*)dst)[i] = u;
    }
}

// ---------------- pad + convert LM head weight ----------------
__global__ void pad_wh_kernel(const float* __restrict__ Wh, unsigned* __restrict__ WhP) {
    int row = blockIdx.y;
    int col = blockIdx.x * 256 + threadIdx.x;
    if (col < VOCAB_P)
        WhP[(size_t)row * VOCAB_P + col] =
            (col < VOCAB) ? f2tf(Wh[(size_t)row * VOCAB + col]) : 0u;
}

// ---------------- embedding ----------------
__global__ void embed_kernel(const int* __restrict__ x, const float* __restrict__ wte,
                             const float* __restrict__ wpe, float* __restrict__ h) {
    int row = blockIdx.x;            // 0..4095
    int tok = x[row];
    int s = row & (SEQ - 1);
    const float* te = wte + (size_t)tok * D_MODEL;
    const float* pe = wpe + (size_t)s * D_MODEL;
    float* out = h + (size_t)row * D_MODEL;
    for (int d = threadIdx.x; d < D_MODEL; d += 256)
        out[d] = te[d] + pe[d];
}

// ---------------- layernorm (single or fused double), tf32 output ----------------
template <bool DOUBLE>
__global__ void ln_kernel(const float* __restrict__ x,
                          const float* __restrict__ w1, const float* __restrict__ b1,
                          const float* __restrict__ w2, const float* __restrict__ b2,
                          unsigned* __restrict__ y) {
    __shared__ float red[256];
    int row = blockIdx.x;
    int tid = threadIdx.x;
    const float* xr = x + (size_t)row * D_MODEL;
    float v0 = xr[tid], v1 = xr[tid + 256], v2 = xr[tid + 512];

    red[tid] = v0 + v1 + v2;
    __syncthreads();
    for (int s = 128; s > 0; s >>= 1) { if (tid < s) red[tid] += red[tid + s]; __syncthreads(); }
    float mean = red[0] * (1.0f / D_MODEL);
    __syncthreads();
    float d0 = v0 - mean, d1 = v1 - mean, d2 = v2 - mean;
    red[tid] = d0 * d0 + d1 * d1 + d2 * d2;
    __syncthreads();
    for (int s = 128; s > 0; s >>= 1) { if (tid < s) red[tid] += red[tid + s]; __syncthreads(); }
    float rstd = rsqrtf(red[0] * (1.0f / D_MODEL) + 1e-5f);
    float y0 = d0 * rstd * w1[tid]       + b1[tid];
    float y1 = d1 * rstd * w1[tid + 256] + b1[tid + 256];
    float y2 = d2 * rstd * w1[tid + 512] + b1[tid + 512];

    if (DOUBLE) {
        __syncthreads();
        red[tid] = y0 + y1 + y2;
        __syncthreads();
        for (int s = 128; s > 0; s >>= 1) { if (tid < s) red[tid] += red[tid + s]; __syncthreads(); }
        float mean2 = red[0] * (1.0f / D_MODEL);
        __syncthreads();
        float e0 = y0 - mean2, e1 = y1 - mean2, e2 = y2 - mean2;
        red[tid] = e0 * e0 + e1 * e1 + e2 * e2;
        __syncthreads();
        for (int s = 128; s > 0; s >>= 1) { if (tid < s) red[tid] += red[tid + s]; __syncthreads(); }
        float rstd2 = rsqrtf(red[0] * (1.0f / D_MODEL) + 1e-5f);
        y0 = e0 * rstd2 * w2[tid]       + b2[tid];
        y1 = e1 * rstd2 * w2[tid + 256] + b2[tid + 256];
        y2 = e2 * rstd2 * w2[tid + 512] + b2[tid + 512];
    }
    unsigned* yr = y + (size_t)row * D_MODEL;
    yr[tid] = f2tf(y0); yr[tid + 256] = f2tf(y1); yr[tid + 512] = f2tf(y2);
}

// ---------------- TF32 tensor-core GEMM body (128x256 tile, 256 threads) ----------------
template <bool GELU, bool RESID, bool HEADED, bool OUTTF>
__device__ __forceinline__
void gemm_body(const unsigned* __restrict__ A, const unsigned* __restrict__ B,
               const float* __restrict__ bias, const float* __restrict__ resid,
               void* __restrict__ Cv, int M, int N, int K, int NC, int bn, int bm) {
    __shared__ unsigned Asf[2][8][2][32][4];   // fragment-order A
    __shared__ unsigned Bs[2][16][264];        // k-major B, 256 cols + pad
    int tid = threadIdx.x;
    int lane = tid & 31, warp = tid >> 5;
    int wm = (warp & 1) * 64;
    int wn = (warp >> 1) * 64;
    int lr = lane >> 2;
    int lc = lane & 3;
    int lane_s = lr * 4 + (lc ^ ((lr >> 1) & 3));

    float acc[4][8][4];
#pragma unroll
    for (int mi = 0; mi < 4; mi++)
#pragma unroll
        for (int ni = 0; ni < 8; ni++)
#pragma unroll
            for (int r = 0; r < 4; r++) acc[mi][ni][r] = 0.f;

    int arow_l = tid >> 1;
    int akc0   = (tid & 1) * 8;
    int aks    = tid & 1;
    int ami    = arow_l >> 4;
    int alr    = arow_l & 7;
    int ahi    = (arow_l >> 3) & 1;
    int asw    = (alr >> 1) & 3;
    int bkr    = tid >> 4;
    int bcl    = (tid & 15) * 4;

    const unsigned* aptr = A + (size_t)(bm * 128 + arow_l) * K + akc0;
    const unsigned* bptr[4];
    int strideB;
    if (HEADED) {
        strideB = 64;
#pragma unroll
        for (int c = 0; c < 4; c++)
            bptr[c] = B + ((size_t)(bn * 4 + c) * K + bkr) * 64 + bcl;
    } else {
        strideB = N;
#pragma unroll
        for (int c = 0; c < 4; c++)
            bptr[c] = B + (size_t)bkr * N + bn * 256 + c * 64 + bcl;
    }
    unsigned bsaddr[2][4];
#pragma unroll
    for (int buf = 0; buf < 2; buf++)
#pragma unroll
        for (int c = 0; c < 4; c++)
            bsaddr[buf][c] = (unsigned)__cvta_generic_to_shared(&Bs[buf][bkr][c * 64 + bcl]);

    uint4 a0, a1;
    auto loadA = [&](int k0) {
        a0 = *(const uint4*)(aptr + k0);
        a1 = *(const uint4*)(aptr + k0 + 4);
    };
    auto storeA = [&](int buf) {
        unsigned* abase = &Asf[buf][ami][aks][0][0];
        unsigned ar[8] = {a0.x, a0.y, a0.z, a0.w, a1.x, a1.y, a1.z, a1.w};
#pragma unroll
        for (int j = 0; j < 8; j++) {
            int ls   = alr * 4 + ((j & 3) ^ asw);
            int slot = ahi + 2 * (j >> 2);
            abase[ls * 4 + slot] = ar[j];
        }
    };
    auto stageB = [&](int k0, int buf) {
#pragma unroll
        for (int c = 0; c < 4; c++)
            cp16(bsaddr[buf][c], bptr[c] + (size_t)k0 * strideB);
        asm volatile("cp.async.commit_group;" ::: "memory");
    };

    stageB(0, 0);
    loadA(0);
    storeA(0);
    asm volatile("cp.async.wait_all;" ::: "memory");
    __syncthreads();

    int cur = 0;
    for (int k0 = 0; k0 < K; k0 += 16) {
        bool has_next = (k0 + 16) < K;
        if (has_next) {
            stageB(k0 + 16, cur ^ 1);
            loadA(k0 + 16);
        }

#pragma unroll
        for (int ks = 0; ks < 2; ks++) {
            int kb = ks * 8;
            unsigned afr[4][4], bfr[8][2];
#pragma unroll
            for (int mi = 0; mi < 4; mi++) {
                int mig = (warp & 1) * 4 + mi;
                uint4 fa = *(const uint4*)&Asf[cur][mig][ks][lane_s][0];
                afr[mi][0] = fa.x; afr[mi][1] = fa.y;
                afr[mi][2] = fa.z; afr[mi][3] = fa.w;
            }
#pragma unroll
            for (int ni = 0; ni < 8; ni++) {
                int n0 = wn + ni * 8;
                bfr[ni][0] = Bs[cur][kb + lc][n0 + lr];
                bfr[ni][1] = Bs[cur][kb + lc + 4][n0 + lr];
            }
#pragma unroll
            for (int mi = 0; mi < 4; mi++)
#pragma unroll
                for (int ni = 0; ni < 8; ni++)
                    mma_tf32(acc[mi][ni], afr[mi], bfr[ni]);
        }

        if (has_next) storeA(cur ^ 1);
        asm volatile("cp.async.wait_all;" ::: "memory");
        __syncthreads();
        cur ^= 1;
    }

    float*    Cf = (float*)Cv;
    unsigned* Cu = (unsigned*)Cv;
#pragma unroll
    for (int mi = 0; mi < 4; mi++) {
        int row0 = bm * 128 + wm + mi * 16 + lr;
#pragma unroll
        for (int ni = 0; ni < 8; ni++) {
            int col = bn * 256 + wn + ni * 8 + lc * 2;
#pragma unroll
            for (int half = 0; half < 2; half++) {
                int row = row0 + half * 8;
#pragma unroll
                for (int cc = 0; cc < 2; cc++) {
                    int c = col + cc;
                    if (c < NC) {
                        float val = acc[mi][ni][half * 2 + cc] + bias[c];
                        if (GELU) val = 0.5f * val * (1.0f + erff(val * 0.70710678118654752f));
                        if (RESID) val += resid[(size_t)row * NC + c];
                        if (OUTTF) Cu[(size_t)row * NC + c] = f2tf(val);
                        else       Cf[(size_t)row * NC + c] = val;
                    }
                }
            }
        }
    }
}

template <bool GELU, bool RESID, bool HEADED, bool OUTTF>
__global__ __launch_bounds__(256, 1)
void gemm_kernel(const unsigned* __restrict__ A, const unsigned* __restrict__ B,
                 const float* __restrict__ bias, const float* __restrict__ resid,
                 void* __restrict__ C, int M, int N, int K, int NC) {
    gemm_body<GELU, RESID, HEADED, OUTTF>(A, B, bias, resid, C, M, N, K, NC,
                                          blockIdx.x, blockIdx.y);
}

// Fused Q/K/V projection: blockIdx.z selects which of the three GEMMs; tf32-bit output.
__global__ __launch_bounds__(256, 1)
void qkv_kernel(const unsigned* __restrict__ A,
                const unsigned* __restrict__ Wq, const unsigned* __restrict__ Wk,
                const unsigned* __restrict__ Wv,
                const float* __restrict__ bq, const float* __restrict__ bk,
                const float* __restrict__ bv,
                unsigned* __restrict__ q, unsigned* __restrict__ k, unsigned* __restrict__ v) {
    const unsigned* B  = (blockIdx.z == 0) ? Wq : (blockIdx.z == 1) ? Wk : Wv;
    const float* bias  = (blockIdx.z == 0) ? bq : (blockIdx.z == 1) ? bk : bv;
    unsigned*    C     = (blockIdx.z == 0) ? q  : (blockIdx.z == 1) ? k  : v;
    gemm_body<false, false, true, true>(A, B, bias, nullptr, C,
                                        ROWS, D_MODEL, D_MODEL, D_MODEL,
                                        blockIdx.x, blockIdx.y);
}

// ---------------- tensor-core causal attention (128-row Q tiles, tf32 mma) ----------------
// 8 warps x 16 Q-rows; per 64-key j-tile: S = Q K^T and O += P V via m16n8k8 tf32 mma.
// Smem: Qs[128][68], Ks[64][68], Vs[64][68], Ps[128][68] (tf32 bits), pad 68 -> conflict-free.
#define ATT_SMEM ((128 * 68 + 64 * 68 + 64 * 68 + 128 * 68) * 4)
__global__ __launch_bounds__(256, 1)
void attn_kernel(const unsigned* __restrict__ q, const unsigned* __restrict__ k,
                 const unsigned* __restrict__ v, unsigned* __restrict__ o) {
    extern __shared__ unsigned smu[];
    unsigned* Qs = smu;                    // [128][68]
    unsigned* Ks = Qs + 128 * 68;          // [64][68]
    unsigned* Vs = Ks + 64 * 68;           // [64][68]
    unsigned* Ps = Vs + 64 * 68;           // [128][68]
    int qi = blockIdx.x, hh = blockIdx.y, b = blockIdx.z;
    int tid = threadIdx.x, lane = tid & 31, warp = tid >> 5;
    int lr = lane >> 2, lc = lane & 3;
    const size_t base = ((size_t)b * SEQ) * D_MODEL + (size_t)hh * HEAD_DIM;
    const float inv_scale = 0.03608439182435161f;   // 1/sqrt(768)

    // stage Q tile (128 rows x 64 dims): 8 uint4 per thread
#pragma unroll
    for (int i = 0; i < 8; i++) {
        int id = tid + 256 * i;
        int r = id >> 4, ch = (id & 15) * 4;
        *(uint4*)&Qs[r * 68 + ch] =
            *(const uint4*)(q + base + (size_t)(qi * 128 + r) * D_MODEL + ch);
    }

    // prefetch K/V tile j=0 (4 uint4 each)
    int str = tid >> 4, se4 = (tid & 15) * 4;
    uint4 kr[4], vr[4];
#pragma unroll
    for (int i = 0; i < 4; i++) {
        int r = str + 16 * i;
        size_t goff = base + (size_t)r * D_MODEL + se4;
        kr[i] = *(const uint4*)(k + goff);
        vr[i] = *(const uint4*)(v + goff);
    }

    float m_[2], l_[2], oacc[8][4];
    m_[0] = m_[1] = -1e30f; l_[0] = l_[1] = 0.f;
#pragma unroll
    for (int ni = 0; ni < 8; ni++)
#pragma unroll
        for (int r = 0; r < 4; r++) oacc[ni][r] = 0.f;

    const unsigned* Qrow = Qs + (warp * 16 + lr) * 68;
    unsigned* Prow0 = Ps + (warp * 16 + lr) * 68;
    unsigned* Prow1 = Prow0 + 8 * 68;

    int jmax = 2 * qi + 1;
    for (int j = 0; j <= jmax; j++) {
        __syncthreads();   // prior PV reads of Ks/Vs done; Qs staged (first iter)
#pragma unroll
        for (int i = 0; i < 4; i++) {
            int r = str + 16 * i;
            *(uint4*)&Ks[r * 68 + se4] = kr[i];
            *(uint4*)&Vs[r * 68 + se4] = vr[i];
        }
        if (j < jmax) {
#pragma unroll
            for (int i = 0; i < 4; i++) {
                int r = str + 16 * i;
                size_t goff = base + (size_t)((j + 1) * 64 + r) * D_MODEL + se4;
                kr[i] = *(const uint4*)(k + goff);
                vr[i] = *(const uint4*)(v + goff);
            }
        }
        __syncthreads();

        // ---- S = Q K^T (16 x 64 per warp) ----
        float s[8][4];
#pragma unroll
        for (int ni = 0; ni < 8; ni++)
#pragma unroll
            for (int r = 0; r < 4; r++) s[ni][r] = 0.f;

#pragma unroll
        for (int ks = 0; ks < 8; ks++) {
            int qoff = ks * 8 + lc;
            unsigned a[4];
            a[0] = Qrow[qoff];
            a[1] = Qrow[8 * 68 + qoff];
            a[2] = Qrow[qoff + 4];
            a[3] = Qrow[8 * 68 + qoff + 4];
#pragma unroll
            for (int ni = 0; ni < 8; ni++) {
                unsigned bfr[2];
                const unsigned* Krow = Ks + (ni * 8 + lr) * 68;
                bfr[0] = Krow[ks * 8 + lc];
                bfr[1] = Krow[ks * 8 + lc + 4];
                mma_tf32(s[ni], a, bfr);
            }
        }

        // ---- scale + mask + online softmax (2 rows per thread) ----
#pragma unroll
        for (int half = 0; half < 2; half++) {
            int qr = qi * 128 + warp * 16 + lr + half * 8;
            float rm = -1e30f;
#pragma unroll
            for (int ni = 0; ni < 8; ni++)
#pragma unroll
                for (int cc = 0; cc < 2; cc++) {
                    float val = s[ni][half * 2 + cc] * inv_scale;
                    int col = j * 64 + ni * 8 + lc * 2 + cc;
                    if (col > qr) val = -1e30f;
                    s[ni][half * 2 + cc] = val;
                    rm = fmaxf(rm, val);
                }
            rm = fmaxf(rm, __shfl_xor_sync(0xffffffffu, rm, 1));
            rm = fmaxf(rm, __shfl_xor_sync(0xffffffffu, rm, 2));
            float mnew = fmaxf(m_[half], rm);
            float alpha = __expf(m_[half] - mnew);
            float psum = 0.f;
#pragma unroll
            for (int ni = 0; ni < 8; ni++)
#pragma unroll
                for (int cc = 0; cc < 2; cc++) {
                    float p = __expf(s[ni][half * 2 + cc] - mnew);
                    s[ni][half * 2 + cc] = p;
                    psum += p;
                }
            psum += __shfl_xor_sync(0xffffffffu, psum, 1);
            psum += __shfl_xor_sync(0xffffffffu, psum, 2);
            l_[half] = l_[half] * alpha + psum;
            m_[half] = mnew;
#pragma unroll
            for (int ni = 0; ni < 8; ni++) {
                oacc[ni][half * 2 + 0] *= alpha;
                oacc[ni][half * 2 + 1] *= alpha;
            }
        }

        // ---- store P (tf32) to own warp's rows; warp-local ----
#pragma unroll
        for (int ni = 0; ni < 8; ni++) {
            Prow0[ni * 8 + lc * 2]     = f2tf(s[ni][0]);
            Prow0[ni * 8 + lc * 2 + 1] = f2tf(s[ni][1]);
            Prow1[ni * 8 + lc * 2]     = f2tf(s[ni][2]);
            Prow1[ni * 8 + lc * 2 + 1] = f2tf(s[ni][3]);
        }
        __syncwarp();

        // ---- O += P V (16 x 64 per warp) ----
#pragma unroll
        for (int ks = 0; ks < 8; ks++) {
            int poff = ks * 8 + lc;
            unsigned a[4];
            a[0] = Prow0[poff];
            a[1] = Prow1[poff];
            a[2] = Prow0[poff + 4];
            a[3] = Prow1[poff + 4];
#pragma unroll
            for (int ni = 0; ni < 8; ni++) {
                unsigned bfr[2];
                bfr[0] = Vs[(ks * 8 + lc) * 68 + ni * 8 + lr];
                bfr[1] = Vs[(ks * 8 + lc + 4) * 68 + ni * 8 + lr];
                mma_tf32(oacc[ni], a, bfr);
            }
        }
    }

    // ---- epilogue: o = f2tf(O / l) ----
    float inv0 = 1.0f / l_[0], inv1 = 1.0f / l_[1];
    int row0 = qi * 128 + warp * 16 + lr;
#pragma unroll
    for (int ni = 0; ni < 8; ni++) {
        int col = ni * 8 + lc * 2;
        unsigned* p0 = o + base + (size_t)row0 * D_MODEL + col;
        unsigned* p1 = o + base + (size_t)(row0 + 8) * D_MODEL + col;
        p0[0] = f2tf(oacc[ni][0] * inv0);
        p0[1] = f2tf(oacc[ni][1] * inv0);
        p1[0] = f2tf(oacc[ni][2] * inv1);
        p1[1] = f2tf(oacc[ni][3] * inv1);
    }
}

// ---------------- launch ----------------
extern "C" void kernel_launch(void* const* d_in, const int* in_sizes, int n_in,
                              void* d_out, int out_size) {
    const int*   x      = (const int*)  d_in[0];
    const float* wte    = (const float*)d_in[1];
    const float* wpe    = (const float*)d_in[2];
    const float* ln1_w  = (const float*)d_in[3];
    const float* ln1_b  = (const float*)d_in[4];
    const float* Wq     = (const float*)d_in[5];
    const float* bq     = (const float*)d_in[6];
    const float* Wk     = (const float*)d_in[7];
    const float* bk     = (const float*)d_in[8];
    const float* Wv     = (const float*)d_in[9];
    const float* bv     = (const float*)d_in[10];
    const float* Wp     = (const float*)d_in[11];
    const float* bp     = (const float*)d_in[12];
    const float* ln2_w  = (const float*)d_in[13];
    const float* ln2_b  = (const float*)d_in[14];
    const float* lnfc_w = (const float*)d_in[15];
    const float* lnfc_b = (const float*)d_in[16];
    const float* W1     = (const float*)d_in[17];
    const float* b1     = (const float*)d_in[18];
    const float* W2     = (const float*)d_in[19];
    const float* b2     = (const float*)d_in[20];
    const float* lnf_w  = (const float*)d_in[21];
    const float* lnf_b  = (const float*)d_in[22];
    const float* Wh     = (const float*)d_in[23];
    const float* bh     = (const float*)d_in[24];
    float* out = (float*)d_out;

    float *h;
    unsigned *a, *q, *k, *v, *o, *m, *whp, *wq, *wk, *wv, *wp, *w1, *w2;
    cudaGetSymbolAddress((void**)&h, g_h);
    cudaGetSymbolAddress((void**)&a, g_a);
    cudaGetSymbolAddress((void**)&q, g_q);
    cudaGetSymbolAddress((void**)&k, g_k);
    cudaGetSymbolAddress((void**)&v, g_v);
    cudaGetSymbolAddress((void**)&o, g_o);
    cudaGetSymbolAddress((void**)&m, g_m);
    cudaGetSymbolAddress((void**)&whp, g_whp);
    cudaGetSymbolAddress((void**)&wq, g_wq);
    cudaGetSymbolAddress((void**)&wk, g_wk);
    cudaGetSymbolAddress((void**)&wv, g_wv);
    cudaGetSymbolAddress((void**)&wp, g_wp);
    cudaGetSymbolAddress((void**)&w1, g_w1);
    cudaGetSymbolAddress((void**)&w2, g_w2);

    cudaFuncSetAttribute(attn_kernel, cudaFuncAttributeMaxDynamicSharedMemorySize, ATT_SMEM);

    // one-time conversions (inside the graph; ~150us total)
    int nW  = N_LAYERS * WSZ / 4;
    int nW4 = N_LAYERS * WSZ;
    cvt_kernel<<<(nW + 255) / 256, 256>>>(Wq, wq, nW);
    cvt_kernel<<<(nW + 255) / 256, 256>>>(Wk, wk, nW);
    cvt_kernel<<<(nW + 255) / 256, 256>>>(Wv, wv, nW);
    cvt_kernel<<<(nW + 255) / 256, 256>>>(Wp, wp, nW);
    cvt_kernel<<<(nW4 + 255) / 256, 256>>>(W1, w1, nW4);
    cvt_kernel<<<(nW4 + 255) / 256, 256>>>(W2, w2, nW4);
    pad_wh_kernel<<<dim3((VOCAB_P + 255) / 256, D_MODEL), 256>>>(Wh, whp);

    embed_kernel<<<ROWS, 256>>>(x, wte, wpe, h);

    dim3 gQKV(D_MODEL / 256, ROWS / 128, 3);          // (3, 32, 3)
    dim3 gProj(D_MODEL / 256, ROWS / 128);            // (3, 32)
    dim3 gFF1(D_FF / 256, ROWS / 128);                // (12, 32)
    dim3 gHead(VOCAB_P / 256, ROWS / 128);            // (197, 32)
    dim3 gAttn(SEQ / 128, N_HEADS, BATCH);            // (8, 12, 4)

    for (int l = 0; l < N_LAYERS; l++) {
        const unsigned* wq_l = wq + (size_t)l * WSZ;
        const unsigned* wk_l = wk + (size_t)l * WSZ;
        const unsigned* wv_l = wv + (size_t)l * WSZ;
        const unsigned* wp_l = wp + (size_t)l * WSZ;
        const unsigned* w1_l = w1 + (size_t)l * WSZ * 4;
        const unsigned* w2_l = w2 + (size_t)l * WSZ * 4;

        ln_kernel<false><<<ROWS, 256>>>(h, ln1_w + l * D_MODEL, ln1_b + l * D_MODEL,
                                        nullptr, nullptr, a);

        qkv_kernel<<<gQKV, 256>>>(a, wq_l, wk_l, wv_l,
                                  bq + l * D_MODEL, bk + l * D_MODEL, bv + l * D_MODEL,
                                  q, k, v);

        attn_kernel<<<gAttn, 256, ATT_SMEM>>>(q, k, v, o);

        gemm_kernel<false, true, false, false><<<gProj, 256>>>(o, wp_l, bp + l * D_MODEL, h, h,
                                                               ROWS, D_MODEL, D_MODEL, D_MODEL);

        ln_kernel<true><<<ROWS, 256>>>(h, ln2_w + l * D_MODEL, ln2_b + l * D_MODEL,
                                       lnfc_w + l * D_MODEL, lnfc_b + l * D_MODEL, a);

        gemm_kernel<true, false, false, true><<<gFF1, 256>>>(a, w1_l, b1 + l * D_FF, nullptr, m,
                                                             ROWS, D_FF, D_MODEL, D_FF);
        gemm_kernel<false, true, false, false><<<gProj, 256>>>(m, w2_l, b2 + l * D_MODEL, h, h,
                                                               ROWS, D_MODEL, D_FF, D_MODEL);
    }

    ln_kernel<false><<<ROWS, 256>>>(h, lnf_w, lnf_b, nullptr, nullptr, a);
    gemm_kernel<false, false, false, false><<<gHead, 256>>>(a, whp, bh, nullptr, out,
                                                            ROWS, VOCAB_P, D_MODEL, VOCAB);
}

// round 11
// speedup vs baseline: 2.2088x; 1.2258x over previous
#include <cuda_runtime.h>
#include <cuda_bf16.h>
#include <math.h>

#define D_MODEL 768
#define N_HEADS 12
#define HEAD_DIM 64
#define N_LAYERS 12
#define SEQ 1024
#define BATCH 4
#define ROWS (BATCH * SEQ)       // 4096
#define D_FF (4 * D_MODEL)       // 3072
#define VOCAB 50257
#define VOCAB_P 50432            // padded to multiple of 256
#define WSZ (D_MODEL * D_MODEL)  // 589824

// dynamic smem for GEMM: Asf 2*8*4*32*4*4B = 32KB, Bs 2*32*264*4B = 66KB
#define ASF_WORDS (2 * 8 * 4 * 32 * 4)       // 8192
#define BS_WORDS  (2 * 32 * 264)             // 16896
#define GEMM_SMEM ((ASF_WORDS + BS_WORDS) * 4)   // 100352 bytes

// ---------------- scratch (device globals; no allocation allowed) ----------------
__device__ float    g_h[ROWS * D_MODEL];
__device__ unsigned g_a[ROWS * D_MODEL];     // tf32 activations (LN out)
__device__ unsigned g_q[ROWS * D_MODEL];
__device__ unsigned g_k[ROWS * D_MODEL];
__device__ unsigned g_v[ROWS * D_MODEL];
__device__ unsigned g_o[ROWS * D_MODEL];     // tf32 attn out
__device__ unsigned g_m[ROWS * D_FF];        // tf32 FF1 out
__device__ float    g_part[3 * ROWS * D_MODEL];  // split-K partials
// tf32 pre-converted weights
__device__ unsigned g_wq[N_LAYERS * WSZ];
__device__ unsigned g_wk[N_LAYERS * WSZ];
__device__ unsigned g_wv[N_LAYERS * WSZ];
__device__ unsigned g_wp[N_LAYERS * WSZ];
__device__ unsigned g_w1[N_LAYERS * WSZ * 4];
__device__ unsigned g_w2[N_LAYERS * WSZ * 4];
__device__ unsigned g_whp[D_MODEL * VOCAB_P];

// ---------------- helpers ----------------
__device__ __forceinline__ unsigned f2tf(float x) {
    unsigned r;
    asm("cvt.rna.tf32.f32 %0, %1;" : "=r"(r) : "f"(x));
    return r;
}

__device__ __forceinline__ void mma_tf32(float* c, const unsigned* a, const unsigned* b) {
    asm volatile(
        "mma.sync.aligned.m16n8k8.row.col.f32.tf32.tf32.f32 "
        "{%0,%1,%2,%3}, {%4,%5,%6,%7}, {%8,%9}, {%0,%1,%2,%3};"
        : "+f"(c[0]), "+f"(c[1]), "+f"(c[2]), "+f"(c[3])
        : "r"(a[0]), "r"(a[1]), "r"(a[2]), "r"(a[3]), "r"(b[0]), "r"(b[1]));
}

__device__ __forceinline__ void cp16(unsigned saddr, const unsigned* gptr) {
    asm volatile("cp.async.cg.shared.global [%0], [%1], 16;"
                 :: "r"(saddr), "l"(gptr) : "memory");
}

// ---------------- weight conversion (fp32 -> tf32 bits), vectorized ----------------
__global__ void cvt_kernel(const float* __restrict__ src, unsigned* __restrict__ dst, int n4) {
    int i = blockIdx.x * 256 + threadIdx.x;
    if (i < n4) {
        float4 v = ((const float4*)src)[i];
        uint4 u;
        u.x = f2tf(v.x); u.y = f2tf(v.y); u.z = f2tf(v.z); u.w = f2tf(v.w);
        ((uint4*)dst)[i] = u;
    }
}

// ---------------- pad + convert LM head weight ----------------
__global__ void pad_wh_kernel(const float* __restrict__ Wh, unsigned* __restrict__ WhP) {
    int row = blockIdx.y;
    int col = blockIdx.x * 256 + threadIdx.x;
    if (col < VOCAB_P)
        WhP[(size_t)row * VOCAB_P + col] =
            (col < VOCAB) ? f2tf(Wh[(size_t)row * VOCAB + col]) : 0u;
}

// ---------------- embedding ----------------
__global__ void embed_kernel(const int* __restrict__ x, const float* __restrict__ wte,
                             const float* __restrict__ wpe, float* __restrict__ h) {
    int row = blockIdx.x;
    int tok = x[row];
    int s = row & (SEQ - 1);
    const float* te = wte + (size_t)tok * D_MODEL;
    const float* pe = wpe + (size_t)s * D_MODEL;
    float* out = h + (size_t)row * D_MODEL;
    for (int d = threadIdx.x; d < D_MODEL; d += 256)
        out[d] = te[d] + pe[d];
}

// ---------------- split-K combine: h += p0+p1+p2+bias (resid = old h) ----------------
__global__ void reduce3_kernel(const float* __restrict__ part, const float* __restrict__ bias,
                               float* __restrict__ h) {
    int row = blockIdx.x;
#pragma unroll
    for (int i = 0; i < 3; i++) {
        int c = threadIdx.x + i * 256;
        size_t idx = (size_t)row * D_MODEL + c;
        h[idx] = part[idx] + part[idx + (size_t)ROWS * D_MODEL]
               + part[idx + 2 * (size_t)ROWS * D_MODEL] + bias[c] + h[idx];
    }
}

// ---------------- layernorm (single or fused double), tf32 output ----------------
template <bool DOUBLE>
__global__ void ln_kernel(const float* __restrict__ x,
                          const float* __restrict__ w1, const float* __restrict__ b1,
                          const float* __restrict__ w2, const float* __restrict__ b2,
                          unsigned* __restrict__ y) {
    __shared__ float red[256];
    int row = blockIdx.x;
    int tid = threadIdx.x;
    const float* xr = x + (size_t)row * D_MODEL;
    float v0 = xr[tid], v1 = xr[tid + 256], v2 = xr[tid + 512];

    red[tid] = v0 + v1 + v2;
    __syncthreads();
    for (int s = 128; s > 0; s >>= 1) { if (tid < s) red[tid] += red[tid + s]; __syncthreads(); }
    float mean = red[0] * (1.0f / D_MODEL);
    __syncthreads();
    float d0 = v0 - mean, d1 = v1 - mean, d2 = v2 - mean;
    red[tid] = d0 * d0 + d1 * d1 + d2 * d2;
    __syncthreads();
    for (int s = 128; s > 0; s >>= 1) { if (tid < s) red[tid] += red[tid + s]; __syncthreads(); }
    float rstd = rsqrtf(red[0] * (1.0f / D_MODEL) + 1e-5f);
    float y0 = d0 * rstd * w1[tid]       + b1[tid];
    float y1 = d1 * rstd * w1[tid + 256] + b1[tid + 256];
    float y2 = d2 * rstd * w1[tid + 512] + b1[tid + 512];

    if (DOUBLE) {
        __syncthreads();
        red[tid] = y0 + y1 + y2;
        __syncthreads();
        for (int s = 128; s > 0; s >>= 1) { if (tid < s) red[tid] += red[tid + s]; __syncthreads(); }
        float mean2 = red[0] * (1.0f / D_MODEL);
        __syncthreads();
        float e0 = y0 - mean2, e1 = y1 - mean2, e2 = y2 - mean2;
        red[tid] = e0 * e0 + e1 * e1 + e2 * e2;
        __syncthreads();
        for (int s = 128; s > 0; s >>= 1) { if (tid < s) red[tid] += red[tid + s]; __syncthreads(); }
        float rstd2 = rsqrtf(red[0] * (1.0f / D_MODEL) + 1e-5f);
        y0 = e0 * rstd2 * w2[tid]       + b2[tid];
        y1 = e1 * rstd2 * w2[tid + 256] + b2[tid + 256];
        y2 = e2 * rstd2 * w2[tid + 512] + b2[tid + 512];
    }
    unsigned* yr = y + (size_t)row * D_MODEL;
    yr[tid] = f2tf(y0); yr[tid + 256] = f2tf(y1); yr[tid + 512] = f2tf(y2);
}

// ---------------- TF32 tensor-core GEMM body (128x256 tile, BK=32, dynamic smem) ----------
// 8 warps, warp tile 64x64; double-buffered k32 stages; B via cp.async; A LDG+scatter.
// PARTIAL: raw fp32 partial output (no bias/act/resid) for split-K.
template <bool GELU, bool RESID, bool HEADED, bool OUTTF, bool PARTIAL>
__device__ __forceinline__
void gemm_body(const unsigned* __restrict__ A, const unsigned* __restrict__ B,
               const float* __restrict__ bias, const float* __restrict__ resid,
               void* __restrict__ Cv, int M, int N, int K, int NC,
               int bn, int bm, int kOff, int kLen) {
    extern __shared__ unsigned smu[];
    unsigned* Asf = smu;                  // [2][8][4][32][4]
    unsigned* Bsm = smu + ASF_WORDS;      // [2][32][264]
    int tid = threadIdx.x;
    int lane = tid & 31, warp = tid >> 5;
    int wm = (warp & 1) * 64;
    int wn = (warp >> 1) * 64;
    int lr = lane >> 2;
    int lc = lane & 3;
    int lane_s = lr * 4 + (lc ^ ((lr >> 1) & 3));

    float acc[4][8][4];
#pragma unroll
    for (int mi = 0; mi < 4; mi++)
#pragma unroll
        for (int ni = 0; ni < 8; ni++)
#pragma unroll
            for (int r = 0; r < 4; r++) acc[mi][ni][r] = 0.f;

    // staging indices
    int arow_l = tid >> 1;                 // 0..127
    int akc0   = (tid & 1) * 16;           // 0 or 16 (two ks halves each)
    int aksb   = (tid & 1) * 2;            // base ks
    int ami    = arow_l >> 4;
    int alr    = arow_l & 7;
    int ahi    = (arow_l >> 3) & 1;
    int asw    = (alr >> 1) & 3;
    int bkr    = tid >> 4;                 // 0..15
    int bcl    = (tid & 15) * 4;

    const unsigned* aptr = A + (size_t)(bm * 128 + arow_l) * K + kOff + akc0;
    const unsigned* bptr[4];
    int strideB;
    if (HEADED) {
        strideB = 64;
#pragma unroll
        for (int c = 0; c < 4; c++)
            bptr[c] = B + ((size_t)(bn * 4 + c) * K + kOff + bkr) * 64 + bcl;
    } else {
        strideB = N;
#pragma unroll
        for (int c = 0; c < 4; c++)
            bptr[c] = B + (size_t)(kOff + bkr) * N + bn * 256 + c * 64 + bcl;
    }
    unsigned bsbase = (unsigned)__cvta_generic_to_shared(Bsm) + (bkr * 264 + bcl) * 4;

    uint4 a0, a1, a2, a3;
    auto loadA = [&](int k0) {
        const unsigned* ap = aptr + k0;
        a0 = *(const uint4*)(ap);
        a1 = *(const uint4*)(ap + 4);
        a2 = *(const uint4*)(ap + 8);
        a3 = *(const uint4*)(ap + 12);
    };
    auto storeA = [&](int buf) {
        unsigned ar[16] = {a0.x, a0.y, a0.z, a0.w, a1.x, a1.y, a1.z, a1.w,
                           a2.x, a2.y, a2.z, a2.w, a3.x, a3.y, a3.z, a3.w};
#pragma unroll
        for (int half = 0; half < 2; half++) {
            int ks = aksb + half;
            unsigned* abase = Asf + (((buf * 8 + ami) * 4 + ks) * 32) * 4;
#pragma unroll
            for (int jj = 0; jj < 8; jj++) {
                int ls   = alr * 4 + ((jj & 3) ^ asw);
                int slot = ahi + 2 * (jj >> 2);
                abase[ls * 4 + slot] = ar[half * 8 + jj];
            }
        }
    };
    auto stageB = [&](int k0, int buf) {
#pragma unroll
        for (int rr = 0; rr < 2; rr++)
#pragma unroll
            for (int c = 0; c < 4; c++)
                cp16(bsbase + (buf * 32 + rr * 16) * 264 * 4 + c * 64 * 4,
                     bptr[c] + (size_t)(k0 + rr * 16) * strideB);
        asm volatile("cp.async.commit_group;" ::: "memory");
    };

    stageB(0, 0);
    loadA(0);
    storeA(0);
    asm volatile("cp.async.wait_all;" ::: "memory");
    __syncthreads();

    int cur = 0;
    for (int k0 = 0; k0 < kLen; k0 += 32) {
        bool has_next = (k0 + 32) < kLen;
        if (has_next) {
            stageB(k0 + 32, cur ^ 1);
            loadA(k0 + 32);
        }

#pragma unroll
        for (int ks = 0; ks < 4; ks++) {
            int kb = ks * 8;
            unsigned afr[4][4], bfr[8][2];
#pragma unroll
            for (int mi = 0; mi < 4; mi++) {
                int mig = (warp & 1) * 4 + mi;
                uint4 fa = *(const uint4*)(Asf + (((cur * 8 + mig) * 4 + ks) * 32 + lane_s) * 4);
                afr[mi][0] = fa.x; afr[mi][1] = fa.y;
                afr[mi][2] = fa.z; afr[mi][3] = fa.w;
            }
#pragma unroll
            for (int ni = 0; ni < 8; ni++) {
                int n0 = wn + ni * 8;
                bfr[ni][0] = Bsm[(cur * 32 + kb + lc) * 264 + n0 + lr];
                bfr[ni][1] = Bsm[(cur * 32 + kb + lc + 4) * 264 + n0 + lr];
            }
#pragma unroll
            for (int mi = 0; mi < 4; mi++)
#pragma unroll
                for (int ni = 0; ni < 8; ni++)
                    mma_tf32(acc[mi][ni], afr[mi], bfr[ni]);
        }

        if (has_next) storeA(cur ^ 1);
        asm volatile("cp.async.wait_all;" ::: "memory");
        __syncthreads();
        cur ^= 1;
    }

    float*    Cf = (float*)Cv;
    unsigned* Cu = (unsigned*)Cv;
#pragma unroll
    for (int mi = 0; mi < 4; mi++) {
        int row0 = bm * 128 + wm + mi * 16 + lr;
#pragma unroll
        for (int ni = 0; ni < 8; ni++) {
            int col = bn * 256 + wn + ni * 8 + lc * 2;
#pragma unroll
            for (int half = 0; half < 2; half++) {
                int row = row0 + half * 8;
#pragma unroll
                for (int cc = 0; cc < 2; cc++) {
                    int c = col + cc;
                    if (c < NC) {
                        float val = acc[mi][ni][half * 2 + cc];
                        if (PARTIAL) {
                            Cf[(size_t)row * NC + c] = val;
                        } else {
                            val += bias[c];
                            if (GELU) val = 0.5f * val * (1.0f + erff(val * 0.70710678118654752f));
                            if (RESID) val += resid[(size_t)row * NC + c];
                            if (OUTTF) Cu[(size_t)row * NC + c] = f2tf(val);
                            else       Cf[(size_t)row * NC + c] = val;
                        }
                    }
                }
            }
        }
    }
}

template <bool GELU, bool RESID, bool HEADED, bool OUTTF, bool PARTIAL>
__global__ __launch_bounds__(256, 1)
void gemm_kernel(const unsigned* __restrict__ A, const unsigned* __restrict__ B,
                 const float* __restrict__ bias, const float* __restrict__ resid,
                 void* __restrict__ C, int M, int N, int K, int NC, int kLen) {
    void* Cv = C;
    int kOff = 0;
    if (PARTIAL) {
        kOff = blockIdx.z * kLen;
        Cv = (float*)C + (size_t)blockIdx.z * M * NC;
    }
    gemm_body<GELU, RESID, HEADED, OUTTF, PARTIAL>(A, B, bias, resid, Cv, M, N, K, NC,
                                                   blockIdx.x, blockIdx.y, kOff, kLen);
}

// Fused Q/K/V projection: blockIdx.z selects which of the three GEMMs; tf32-bit output.
__global__ __launch_bounds__(256, 1)
void qkv_kernel(const unsigned* __restrict__ A,
                const unsigned* __restrict__ Wq, const unsigned* __restrict__ Wk,
                const unsigned* __restrict__ Wv,
                const float* __restrict__ bq, const float* __restrict__ bk,
                const float* __restrict__ bv,
                unsigned* __restrict__ q, unsigned* __restrict__ k, unsigned* __restrict__ v) {
    const unsigned* B  = (blockIdx.z == 0) ? Wq : (blockIdx.z == 1) ? Wk : Wv;
    const float* bias  = (blockIdx.z == 0) ? bq : (blockIdx.z == 1) ? bk : bv;
    unsigned*    C     = (blockIdx.z == 0) ? q  : (blockIdx.z == 1) ? k  : v;
    gemm_body<false, false, true, true, false>(A, B, bias, nullptr, C,
                                               ROWS, D_MODEL, D_MODEL, D_MODEL,
                                               blockIdx.x, blockIdx.y, 0, D_MODEL);
}

// ---------------- tensor-core causal attention (128-row Q tiles, tf32 mma) ----------------
#define ATT_SMEM ((128 * 68 + 64 * 68 + 64 * 68 + 128 * 68) * 4)
__global__ __launch_bounds__(256, 1)
void attn_kernel(const unsigned* __restrict__ q, const unsigned* __restrict__ k,
                 const unsigned* __restrict__ v, unsigned* __restrict__ o) {
    extern __shared__ unsigned smu[];
    unsigned* Qs = smu;
    unsigned* Ks = Qs + 128 * 68;
    unsigned* Vs = Ks + 64 * 68;
    unsigned* Ps = Vs + 64 * 68;
    int qi = blockIdx.x, hh = blockIdx.y, b = blockIdx.z;
    int tid = threadIdx.x, lane = tid & 31, warp = tid >> 5;
    int lr = lane >> 2, lc = lane & 3;
    const size_t base = ((size_t)b * SEQ) * D_MODEL + (size_t)hh * HEAD_DIM;
    const float inv_scale = 0.03608439182435161f;   // 1/sqrt(768)

#pragma unroll
    for (int i = 0; i < 8; i++) {
        int id = tid + 256 * i;
        int r = id >> 4, ch = (id & 15) * 4;
        *(uint4*)&Qs[r * 68 + ch] =
            *(const uint4*)(q + base + (size_t)(qi * 128 + r) * D_MODEL + ch);
    }

    int str = tid >> 4, se4 = (tid & 15) * 4;
    uint4 kr[4], vr[4];
#pragma unroll
    for (int i = 0; i < 4; i++) {
        int r = str + 16 * i;
        size_t goff = base + (size_t)r * D_MODEL + se4;
        kr[i] = *(const uint4*)(k + goff);
        vr[i] = *(const uint4*)(v + goff);
    }

    float m_[2], l_[2], oacc[8][4];
    m_[0] = m_[1] = -1e30f; l_[0] = l_[1] = 0.f;
#pragma unroll
    for (int ni = 0; ni < 8; ni++)
#pragma unroll
        for (int r = 0; r < 4; r++) oacc[ni][r] = 0.f;

    const unsigned* Qrow = Qs + (warp * 16 + lr) * 68;
    unsigned* Prow0 = Ps + (warp * 16 + lr) * 68;
    unsigned* Prow1 = Prow0 + 8 * 68;

    int jmax = 2 * qi + 1;
    for (int j = 0; j <= jmax; j++) {
        __syncthreads();
#pragma unroll
        for (int i = 0; i < 4; i++) {
            int r = str + 16 * i;
            *(uint4*)&Ks[r * 68 + se4] = kr[i];
            *(uint4*)&Vs[r * 68 + se4] = vr[i];
        }
        if (j < jmax) {
#pragma unroll
            for (int i = 0; i < 4; i++) {
                int r = str + 16 * i;
                size_t goff = base + (size_t)((j + 1) * 64 + r) * D_MODEL + se4;
                kr[i] = *(const uint4*)(k + goff);
                vr[i] = *(const uint4*)(v + goff);
            }
        }
        __syncthreads();

        float s[8][4];
#pragma unroll
        for (int ni = 0; ni < 8; ni++)
#pragma unroll
            for (int r = 0; r < 4; r++) s[ni][r] = 0.f;

#pragma unroll
        for (int ks = 0; ks < 8; ks++) {
            int qoff = ks * 8 + lc;
            unsigned a[4];
            a[0] = Qrow[qoff];
            a[1] = Qrow[8 * 68 + qoff];
            a[2] = Qrow[qoff + 4];
            a[3] = Qrow[8 * 68 + qoff + 4];
#pragma unroll
            for (int ni = 0; ni < 8; ni++) {
                unsigned bfr[2];
                const unsigned* Krow = Ks + (ni * 8 + lr) * 68;
                bfr[0] = Krow[ks * 8 + lc];
                bfr[1] = Krow[ks * 8 + lc + 4];
                mma_tf32(s[ni], a, bfr);
            }
        }

#pragma unroll
        for (int half = 0; half < 2; half++) {
            int qr = qi * 128 + warp * 16 + lr + half * 8;
            float rm = -1e30f;
#pragma unroll
            for (int ni = 0; ni < 8; ni++)
#pragma unroll
                for (int cc = 0; cc < 2; cc++) {
                    float val = s[ni][half * 2 + cc] * inv_scale;
                    int col = j * 64 + ni * 8 + lc * 2 + cc;
                    if (col > qr) val = -1e30f;
                    s[ni][half * 2 + cc] = val;
                    rm = fmaxf(rm, val);
                }
            rm = fmaxf(rm, __shfl_xor_sync(0xffffffffu, rm, 1));
            rm = fmaxf(rm, __shfl_xor_sync(0xffffffffu, rm, 2));
            float mnew = fmaxf(m_[half], rm);
            float alpha = __expf(m_[half] - mnew);
            float psum = 0.f;
#pragma unroll
            for (int ni = 0; ni < 8; ni++)
#pragma unroll
                for (int cc = 0; cc < 2; cc++) {
                    float p = __expf(s[ni][half * 2 + cc] - mnew);
                    s[ni][half * 2 + cc] = p;
                    psum += p;
                }
            psum += __shfl_xor_sync(0xffffffffu, psum, 1);
            psum += __shfl_xor_sync(0xffffffffu, psum, 2);
            l_[half] = l_[half] * alpha + psum;
            m_[half] = mnew;
#pragma unroll
            for (int ni = 0; ni < 8; ni++) {
                oacc[ni][half * 2 + 0] *= alpha;
                oacc[ni][half * 2 + 1] *= alpha;
            }
        }

#pragma unroll
        for (int ni = 0; ni < 8; ni++) {
            Prow0[ni * 8 + lc * 2]     = f2tf(s[ni][0]);
            Prow0[ni * 8 + lc * 2 + 1] = f2tf(s[ni][1]);
            Prow1[ni * 8 + lc * 2]     = f2tf(s[ni][2]);
            Prow1[ni * 8 + lc * 2 + 1] = f2tf(s[ni][3]);
        }
        __syncwarp();

#pragma unroll
        for (int ks = 0; ks < 8; ks++) {
            int poff = ks * 8 + lc;
            unsigned a[4];
            a[0] = Prow0[poff];
            a[1] = Prow1[poff];
            a[2] = Prow0[poff + 4];
            a[3] = Prow1[poff + 4];
#pragma unroll
            for (int ni = 0; ni < 8; ni++) {
                unsigned bfr[2];
                bfr[0] = Vs[(ks * 8 + lc) * 68 + ni * 8 + lr];
                bfr[1] = Vs[(ks * 8 + lc + 4) * 68 + ni * 8 + lr];
                mma_tf32(oacc[ni], a, bfr);
            }
        }
    }

    float inv0 = 1.0f / l_[0], inv1 = 1.0f / l_[1];
    int row0 = qi * 128 + warp * 16 + lr;
#pragma unroll
    for (int ni = 0; ni < 8; ni++) {
        int col = ni * 8 + lc * 2;
        unsigned* p0 = o + base + (size_t)row0 * D_MODEL + col;
        unsigned* p1 = o + base + (size_t)(row0 + 8) * D_MODEL + col;
        p0[0] = f2tf(oacc[ni][0] * inv0);
        p0[1] = f2tf(oacc[ni][1] * inv0);
        p1[0] = f2tf(oacc[ni][2] * inv1);
        p1[1] = f2tf(oacc[ni][3] * inv1);
    }
}

// ---------------- launch ----------------
extern "C" void kernel_launch(void* const* d_in, const int* in_sizes, int n_in,
                              void* d_out, int out_size) {
    const int*   x      = (const int*)  d_in[0];
    const float* wte    = (const float*)d_in[1];
    const float* wpe    = (const float*)d_in[2];
    const float* ln1_w  = (const float*)d_in[3];
    const float* ln1_b  = (const float*)d_in[4];
    const float* Wq     = (const float*)d_in[5];
    const float* bq     = (const float*)d_in[6];
    const float* Wk     = (const float*)d_in[7];
    const float* bk     = (const float*)d_in[8];
    const float* Wv     = (const float*)d_in[9];
    const float* bv     = (const float*)d_in[10];
    const float* Wp     = (const float*)d_in[11];
    const float* bp     = (const float*)d_in[12];
    const float* ln2_w  = (const float*)d_in[13];
    const float* ln2_b  = (const float*)d_in[14];
    const float* lnfc_w = (const float*)d_in[15];
    const float* lnfc_b = (const float*)d_in[16];
    const float* W1     = (const float*)d_in[17];
    const float* b1     = (const float*)d_in[18];
    const float* W2     = (const float*)d_in[19];
    const float* b2     = (const float*)d_in[20];
    const float* lnf_w  = (const float*)d_in[21];
    const float* lnf_b  = (const float*)d_in[22];
    const float* Wh     = (const float*)d_in[23];
    const float* bh     = (const float*)d_in[24];
    float* out = (float*)d_out;

    float *h, *part;
    unsigned *a, *q, *k, *v, *o, *m, *whp, *wq, *wk, *wv, *wp, *w1, *w2;
    cudaGetSymbolAddress((void**)&h, g_h);
    cudaGetSymbolAddress((void**)&a, g_a);
    cudaGetSymbolAddress((void**)&q, g_q);
    cudaGetSymbolAddress((void**)&k, g_k);
    cudaGetSymbolAddress((void**)&v, g_v);
    cudaGetSymbolAddress((void**)&o, g_o);
    cudaGetSymbolAddress((void**)&m, g_m);
    cudaGetSymbolAddress((void**)&part, g_part);
    cudaGetSymbolAddress((void**)&whp, g_whp);
    cudaGetSymbolAddress((void**)&wq, g_wq);
    cudaGetSymbolAddress((void**)&wk, g_wk);
    cudaGetSymbolAddress((void**)&wv, g_wv);
    cudaGetSymbolAddress((void**)&wp, g_wp);
    cudaGetSymbolAddress((void**)&w1, g_w1);
    cudaGetSymbolAddress((void**)&w2, g_w2);

    cudaFuncSetAttribute(attn_kernel, cudaFuncAttributeMaxDynamicSharedMemorySize, ATT_SMEM);
    cudaFuncSetAttribute(qkv_kernel, cudaFuncAttributeMaxDynamicSharedMemorySize, GEMM_SMEM);
    cudaFuncSetAttribute(gemm_kernel<true, false, false, true, false>,
                         cudaFuncAttributeMaxDynamicSharedMemorySize, GEMM_SMEM);   // FF1
    cudaFuncSetAttribute(gemm_kernel<false, false, false, false, false>,
                         cudaFuncAttributeMaxDynamicSharedMemorySize, GEMM_SMEM);   // head
    cudaFuncSetAttribute(gemm_kernel<false, false, false, false, true>,
                         cudaFuncAttributeMaxDynamicSharedMemorySize, GEMM_SMEM);   // split-K

    // one-time conversions
    int nW  = N_LAYERS * WSZ / 4;
    int nW4 = N_LAYERS * WSZ;
    cvt_kernel<<<(nW + 255) / 256, 256>>>(Wq, wq, nW);
    cvt_kernel<<<(nW + 255) / 256, 256>>>(Wk, wk, nW);
    cvt_kernel<<<(nW + 255) / 256, 256>>>(Wv, wv, nW);
    cvt_kernel<<<(nW + 255) / 256, 256>>>(Wp, wp, nW);
    cvt_kernel<<<(nW4 + 255) / 256, 256>>>(W1, w1, nW4);
    cvt_kernel<<<(nW4 + 255) / 256, 256>>>(W2, w2, nW4);
    pad_wh_kernel<<<dim3((VOCAB_P + 255) / 256, D_MODEL), 256>>>(Wh, whp);

    embed_kernel<<<ROWS, 256>>>(x, wte, wpe, h);

    dim3 gQKV(D_MODEL / 256, ROWS / 128, 3);          // (3, 32, 3)
    dim3 gSplit(D_MODEL / 256, ROWS / 128, 3);        // (3, 32, 3) split-K
    dim3 gFF1(D_FF / 256, ROWS / 128);                // (12, 32)
    dim3 gHead(VOCAB_P / 256, ROWS / 128);            // (197, 32)
    dim3 gAttn(SEQ / 128, N_HEADS, BATCH);            // (8, 12, 4)

    for (int l = 0; l < N_LAYERS; l++) {
        const unsigned* wq_l = wq + (size_t)l * WSZ;
        const unsigned* wk_l = wk + (size_t)l * WSZ;
        const unsigned* wv_l = wv + (size_t)l * WSZ;
        const unsigned* wp_l = wp + (size_t)l * WSZ;
        const unsigned* w1_l = w1 + (size_t)l * WSZ * 4;
        const unsigned* w2_l = w2 + (size_t)l * WSZ * 4;

        ln_kernel<false><<<ROWS, 256>>>(h, ln1_w + l * D_MODEL, ln1_b + l * D_MODEL,
                                        nullptr, nullptr, a);

        qkv_kernel<<<gQKV, 256, GEMM_SMEM>>>(a, wq_l, wk_l, wv_l,
                                             bq + l * D_MODEL, bk + l * D_MODEL, bv + l * D_MODEL,
                                             q, k, v);

        attn_kernel<<<gAttn, 256, ATT_SMEM>>>(q, k, v, o);

        // proj: split-K x3 (K=768 -> 256 each) + deterministic reduce into h
        gemm_kernel<false, false, false, false, true><<<gSplit, 256, GEMM_SMEM>>>(
            o, wp_l, nullptr, nullptr, part, ROWS, D_MODEL, D_MODEL, D_MODEL, 256);
        reduce3_kernel<<<ROWS, 256>>>(part, bp + l * D_MODEL, h);

        ln_kernel<true><<<ROWS, 256>>>(h, ln2_w + l * D_MODEL, ln2_b + l * D_MODEL,
                                       lnfc_w + l * D_MODEL, lnfc_b + l * D_MODEL, a);

        gemm_kernel<true, false, false, true, false><<<gFF1, 256, GEMM_SMEM>>>(
            a, w1_l, b1 + l * D_FF, nullptr, m, ROWS, D_FF, D_MODEL, D_FF, D_MODEL);

        // FF2: split-K x3 (K=3072 -> 1024 each) + reduce into h
        gemm_kernel<false, false, false, false, true><<<gSplit, 256, GEMM_SMEM>>>(
            m, w2_l, nullptr, nullptr, part, ROWS, D_MODEL, D_FF, D_MODEL, 1024);
        reduce3_kernel<<<ROWS, 256>>>(part, b2 + l * D_MODEL, h);
    }

    ln_kernel<false><<<ROWS, 256>>>(h, lnf_w, lnf_b, nullptr, nullptr, a);
    gemm_kernel<false, false, false, false, false><<<gHead, 256, GEMM_SMEM>>>(
        a, whp, bh, nullptr, out, ROWS, VOCAB_P, D_MODEL, VOCAB, D_MODEL);
}

// round 12
// speedup vs baseline: 2.2140x; 1.0024x over previous
#include <cuda_runtime.h>
#include <cuda_bf16.h>
#include <math.h>

#define D_MODEL 768
#define N_HEADS 12
#define HEAD_DIM 64
#define N_LAYERS 12
#define SEQ 1024
#define BATCH 4
#define ROWS (BATCH * SEQ)       // 4096
#define D_FF (4 * D_MODEL)       // 3072
#define VOCAB 50257
#define VOCAB_P 50432            // padded to multiple of 256
#define WSZ (D_MODEL * D_MODEL)  // 589824

// dynamic smem for GEMM: Asf 2*8*4*32*4*4B = 32KB, Bs 2*32*264*4B = 66KB
#define ASF_WORDS (2 * 8 * 4 * 32 * 4)       // 8192
#define BS_WORDS  (2 * 32 * 264)             // 16896
#define GEMM_SMEM ((ASF_WORDS + BS_WORDS) * 4)   // 100352 bytes

// ---------------- scratch (device globals; no allocation allowed) ----------------
__device__ float    g_h[ROWS * D_MODEL];
__device__ unsigned g_a[ROWS * D_MODEL];     // tf32 activations (LN out)
__device__ unsigned g_q[ROWS * D_MODEL];
__device__ unsigned g_k[ROWS * D_MODEL];
__device__ unsigned g_v[ROWS * D_MODEL];
__device__ unsigned g_o[ROWS * D_MODEL];     // tf32 attn out
__device__ unsigned g_m[ROWS * D_FF];        // tf32 FF1 out
__device__ float    g_part[3 * ROWS * D_MODEL];  // split-K partials
// tf32 pre-converted weights
__device__ unsigned g_wq[N_LAYERS * WSZ];
__device__ unsigned g_wk[N_LAYERS * WSZ];
__device__ unsigned g_wv[N_LAYERS * WSZ];
__device__ unsigned g_wp[N_LAYERS * WSZ];
__device__ unsigned g_w1[N_LAYERS * WSZ * 4];
__device__ unsigned g_w2[N_LAYERS * WSZ * 4];
__device__ unsigned g_whp[D_MODEL * VOCAB_P];

// ---------------- helpers ----------------
__device__ __forceinline__ unsigned f2tf(float x) {
    unsigned r;
    asm("cvt.rna.tf32.f32 %0, %1;" : "=r"(r) : "f"(x));
    return r;
}

__device__ __forceinline__ void mma_tf32(float* c, const unsigned* a, const unsigned* b) {
    asm volatile(
        "mma.sync.aligned.m16n8k8.row.col.f32.tf32.tf32.f32 "
        "{%0,%1,%2,%3}, {%4,%5,%6,%7}, {%8,%9}, {%0,%1,%2,%3};"
        : "+f"(c[0]), "+f"(c[1]), "+f"(c[2]), "+f"(c[3])
        : "r"(a[0]), "r"(a[1]), "r"(a[2]), "r"(a[3]), "r"(b[0]), "r"(b[1]));
}

__device__ __forceinline__ void cp16(unsigned saddr, const unsigned* gptr) {
    asm volatile("cp.async.cg.shared.global [%0], [%1], 16;"
                 :: "r"(saddr), "l"(gptr) : "memory");
}

// ---------------- weight conversion (fp32 -> tf32 bits), vectorized ----------------
__global__ void cvt_kernel(const float* __restrict__ src, unsigned* __restrict__ dst, int n4) {
    int i = blockIdx.x * 256 + threadIdx.x;
    if (i < n4) {
        float4 v = ((const float4*)src)[i];
        uint4 u;
        u.x = f2tf(v.x); u.y = f2tf(v.y); u.z = f2tf(v.z); u.w = f2tf(v.w);
        ((uint4*)dst)[i] = u;
    }
}

// ---------------- pad + convert LM head weight ----------------
__global__ void pad_wh_kernel(const float* __restrict__ Wh, unsigned* __restrict__ WhP) {
    int row = blockIdx.y;
    int col = blockIdx.x * 256 + threadIdx.x;
    if (col < VOCAB_P)
        WhP[(size_t)row * VOCAB_P + col] =
            (col < VOCAB) ? f2tf(Wh[(size_t)row * VOCAB + col]) : 0u;
}

// ---------------- embedding ----------------
__global__ void embed_kernel(const int* __restrict__ x, const float* __restrict__ wte,
                             const float* __restrict__ wpe, float* __restrict__ h) {
    int row = blockIdx.x;
    int tok = x[row];
    int s = row & (SEQ - 1);
    const float* te = wte + (size_t)tok * D_MODEL;
    const float* pe = wpe + (size_t)s * D_MODEL;
    float* out = h + (size_t)row * D_MODEL;
    for (int d = threadIdx.x; d < D_MODEL; d += 256)
        out[d] = te[d] + pe[d];
}

// ---------------- LN core (shared by ln_kernel / lnred_kernel) ----------------
template <bool DOUBLE>
__device__ __forceinline__
void ln_core(float v0, float v1, float v2,
             const float* __restrict__ w1, const float* __restrict__ b1,
             const float* __restrict__ w2, const float* __restrict__ b2,
             unsigned* __restrict__ yr, float* red, int tid) {
    red[tid] = v0 + v1 + v2;
    __syncthreads();
    for (int s = 128; s > 0; s >>= 1) { if (tid < s) red[tid] += red[tid + s]; __syncthreads(); }
    float mean = red[0] * (1.0f / D_MODEL);
    __syncthreads();
    float d0 = v0 - mean, d1 = v1 - mean, d2 = v2 - mean;
    red[tid] = d0 * d0 + d1 * d1 + d2 * d2;
    __syncthreads();
    for (int s = 128; s > 0; s >>= 1) { if (tid < s) red[tid] += red[tid + s]; __syncthreads(); }
    float rstd = rsqrtf(red[0] * (1.0f / D_MODEL) + 1e-5f);
    float y0 = d0 * rstd * w1[tid]       + b1[tid];
    float y1 = d1 * rstd * w1[tid + 256] + b1[tid + 256];
    float y2 = d2 * rstd * w1[tid + 512] + b1[tid + 512];

    if (DOUBLE) {
        __syncthreads();
        red[tid] = y0 + y1 + y2;
        __syncthreads();
        for (int s = 128; s > 0; s >>= 1) { if (tid < s) red[tid] += red[tid + s]; __syncthreads(); }
        float mean2 = red[0] * (1.0f / D_MODEL);
        __syncthreads();
        float e0 = y0 - mean2, e1 = y1 - mean2, e2 = y2 - mean2;
        red[tid] = e0 * e0 + e1 * e1 + e2 * e2;
        __syncthreads();
        for (int s = 128; s > 0; s >>= 1) { if (tid < s) red[tid] += red[tid + s]; __syncthreads(); }
        float rstd2 = rsqrtf(red[0] * (1.0f / D_MODEL) + 1e-5f);
        y0 = e0 * rstd2 * w2[tid]       + b2[tid];
        y1 = e1 * rstd2 * w2[tid + 256] + b2[tid + 256];
        y2 = e2 * rstd2 * w2[tid + 512] + b2[tid + 512];
    }
    yr[tid] = f2tf(y0); yr[tid + 256] = f2tf(y1); yr[tid + 512] = f2tf(y2);
}

// plain LN (layer-0 ln1 only)
template <bool DOUBLE>
__global__ void ln_kernel(const float* __restrict__ x,
                          const float* __restrict__ w1, const float* __restrict__ b1,
                          const float* __restrict__ w2, const float* __restrict__ b2,
                          unsigned* __restrict__ y) {
    __shared__ float red[256];
    int row = blockIdx.x, tid = threadIdx.x;
    const float* xr = x + (size_t)row * D_MODEL;
    ln_core<DOUBLE>(xr[tid], xr[tid + 256], xr[tid + 512],
                    w1, b1, w2, b2, y + (size_t)row * D_MODEL, red, tid);
}

// fused split-K reduce + residual + LN: h = p0+p1+p2+bias+h; y = LN(h)
template <bool DOUBLE>
__global__ void lnred_kernel(const float* __restrict__ part, const float* __restrict__ bias,
                             float* __restrict__ h,
                             const float* __restrict__ w1, const float* __restrict__ b1,
                             const float* __restrict__ w2, const float* __restrict__ b2,
                             unsigned* __restrict__ y) {
    __shared__ float red[256];
    int row = blockIdx.x, tid = threadIdx.x;
    float v[3];
#pragma unroll
    for (int i = 0; i < 3; i++) {
        int c = tid + i * 256;
        size_t idx = (size_t)row * D_MODEL + c;
        v[i] = part[idx] + part[idx + (size_t)ROWS * D_MODEL]
             + part[idx + 2 * (size_t)ROWS * D_MODEL] + bias[c] + h[idx];
        h[idx] = v[i];
    }
    ln_core<DOUBLE>(v[0], v[1], v[2], w1, b1, w2, b2,
                    y + (size_t)row * D_MODEL, red, tid);
}

// ---------------- TF32 tensor-core GEMM body (128x256 tile, BK=32, dynamic smem) ----------
template <bool GELU, bool RESID, bool HEADED, bool OUTTF, bool PARTIAL>
__device__ __forceinline__
void gemm_body(const unsigned* __restrict__ A, const unsigned* __restrict__ B,
               const float* __restrict__ bias, const float* __restrict__ resid,
               void* __restrict__ Cv, int M, int N, int K, int NC,
               int bn, int bm, int kOff, int kLen) {
    extern __shared__ unsigned smu[];
    unsigned* Asf = smu;                  // [2][8][4][32][4]
    unsigned* Bsm = smu + ASF_WORDS;      // [2][32][264]
    int tid = threadIdx.x;
    int lane = tid & 31, warp = tid >> 5;
    int wm = (warp & 1) * 64;
    int wn = (warp >> 1) * 64;
    int lr = lane >> 2;
    int lc = lane & 3;
    int lane_s = lr * 4 + (lc ^ ((lr >> 1) & 3));

    float acc[4][8][4];
#pragma unroll
    for (int mi = 0; mi < 4; mi++)
#pragma unroll
        for (int ni = 0; ni < 8; ni++)
#pragma unroll
            for (int r = 0; r < 4; r++) acc[mi][ni][r] = 0.f;

    int arow_l = tid >> 1;
    int akc0   = (tid & 1) * 16;
    int aksb   = (tid & 1) * 2;
    int ami    = arow_l >> 4;
    int alr    = arow_l & 7;
    int ahi    = (arow_l >> 3) & 1;
    int asw    = (alr >> 1) & 3;
    int bkr    = tid >> 4;
    int bcl    = (tid & 15) * 4;

    const unsigned* aptr = A + (size_t)(bm * 128 + arow_l) * K + kOff + akc0;
    const unsigned* bptr[4];
    int strideB;
    if (HEADED) {
        strideB = 64;
#pragma unroll
        for (int c = 0; c < 4; c++)
            bptr[c] = B + ((size_t)(bn * 4 + c) * K + kOff + bkr) * 64 + bcl;
    } else {
        strideB = N;
#pragma unroll
        for (int c = 0; c < 4; c++)
            bptr[c] = B + (size_t)(kOff + bkr) * N + bn * 256 + c * 64 + bcl;
    }
    unsigned bsbase = (unsigned)__cvta_generic_to_shared(Bsm) + (bkr * 264 + bcl) * 4;

    uint4 a0, a1, a2, a3;
    auto loadA = [&](int k0) {
        const unsigned* ap = aptr + k0;
        a0 = *(const uint4*)(ap);
        a1 = *(const uint4*)(ap + 4);
        a2 = *(const uint4*)(ap + 8);
        a3 = *(const uint4*)(ap + 12);
    };
    auto storeA = [&](int buf) {
        unsigned ar[16] = {a0.x, a0.y, a0.z, a0.w, a1.x, a1.y, a1.z, a1.w,
                           a2.x, a2.y, a2.z, a2.w, a3.x, a3.y, a3.z, a3.w};
#pragma unroll
        for (int half = 0; half < 2; half++) {
            int ks = aksb + half;
            unsigned* abase = Asf + (((buf * 8 + ami) * 4 + ks) * 32) * 4;
#pragma unroll
            for (int jj = 0; jj < 8; jj++) {
                int ls   = alr * 4 + ((jj & 3) ^ asw);
                int slot = ahi + 2 * (jj >> 2);
                abase[ls * 4 + slot] = ar[half * 8 + jj];
            }
        }
    };
    auto stageB = [&](int k0, int buf) {
#pragma unroll
        for (int rr = 0; rr < 2; rr++)
#pragma unroll
            for (int c = 0; c < 4; c++)
                cp16(bsbase + (buf * 32 + rr * 16) * 264 * 4 + c * 64 * 4,
                     bptr[c] + (size_t)(k0 + rr * 16) * strideB);
        asm volatile("cp.async.commit_group;" ::: "memory");
    };

    stageB(0, 0);
    loadA(0);
    storeA(0);
    asm volatile("cp.async.wait_all;" ::: "memory");
    __syncthreads();

    int cur = 0;
    for (int k0 = 0; k0 < kLen; k0 += 32) {
        bool has_next = (k0 + 32) < kLen;
        if (has_next) {
            stageB(k0 + 32, cur ^ 1);
            loadA(k0 + 32);
        }

#pragma unroll
        for (int ks = 0; ks < 4; ks++) {
            int kb = ks * 8;
            unsigned afr[4][4], bfr[8][2];
#pragma unroll
            for (int mi = 0; mi < 4; mi++) {
                int mig = (warp & 1) * 4 + mi;
                uint4 fa = *(const uint4*)(Asf + (((cur * 8 + mig) * 4 + ks) * 32 + lane_s) * 4);
                afr[mi][0] = fa.x; afr[mi][1] = fa.y;
                afr[mi][2] = fa.z; afr[mi][3] = fa.w;
            }
#pragma unroll
            for (int ni = 0; ni < 8; ni++) {
                int n0 = wn + ni * 8;
                bfr[ni][0] = Bsm[(cur * 32 + kb + lc) * 264 + n0 + lr];
                bfr[ni][1] = Bsm[(cur * 32 + kb + lc + 4) * 264 + n0 + lr];
            }
#pragma unroll
            for (int mi = 0; mi < 4; mi++)
#pragma unroll
                for (int ni = 0; ni < 8; ni++)
                    mma_tf32(acc[mi][ni], afr[mi], bfr[ni]);
        }

        if (has_next) storeA(cur ^ 1);
        asm volatile("cp.async.wait_all;" ::: "memory");
        __syncthreads();
        cur ^= 1;
    }

    float*    Cf = (float*)Cv;
    unsigned* Cu = (unsigned*)Cv;
#pragma unroll
    for (int mi = 0; mi < 4; mi++) {
        int row0 = bm * 128 + wm + mi * 16 + lr;
#pragma unroll
        for (int ni = 0; ni < 8; ni++) {
            int col = bn * 256 + wn + ni * 8 + lc * 2;
#pragma unroll
            for (int half = 0; half < 2; half++) {
                int row = row0 + half * 8;
#pragma unroll
                for (int cc = 0; cc < 2; cc++) {
                    int c = col + cc;
                    if (c < NC) {
                        float val = acc[mi][ni][half * 2 + cc];
                        if (PARTIAL) {
                            Cf[(size_t)row * NC + c] = val;
                        } else {
                            val += bias[c];
                            if (GELU) val = 0.5f * val * (1.0f + erff(val * 0.70710678118654752f));
                            if (RESID) val += resid[(size_t)row * NC + c];
                            if (OUTTF) Cu[(size_t)row * NC + c] = f2tf(val);
                            else       Cf[(size_t)row * NC + c] = val;
                        }
                    }
                }
            }
        }
    }
}

template <bool GELU, bool RESID, bool HEADED, bool OUTTF, bool PARTIAL>
__global__ __launch_bounds__(256, 1)
void gemm_kernel(const unsigned* __restrict__ A, const unsigned* __restrict__ B,
                 const float* __restrict__ bias, const float* __restrict__ resid,
                 void* __restrict__ C, int M, int N, int K, int NC, int kLen) {
    void* Cv = C;
    int kOff = 0;
    if (PARTIAL) {
        kOff = blockIdx.z * kLen;
        Cv = (float*)C + (size_t)blockIdx.z * M * NC;
    }
    gemm_body<GELU, RESID, HEADED, OUTTF, PARTIAL>(A, B, bias, resid, Cv, M, N, K, NC,
                                                   blockIdx.x, blockIdx.y, kOff, kLen);
}

// Fused Q/K/V projection
__global__ __launch_bounds__(256, 1)
void qkv_kernel(const unsigned* __restrict__ A,
                const unsigned* __restrict__ Wq, const unsigned* __restrict__ Wk,
                const unsigned* __restrict__ Wv,
                const float* __restrict__ bq, const float* __restrict__ bk,
                const float* __restrict__ bv,
                unsigned* __restrict__ q, unsigned* __restrict__ k, unsigned* __restrict__ v) {
    const unsigned* B  = (blockIdx.z == 0) ? Wq : (blockIdx.z == 1) ? Wk : Wv;
    const float* bias  = (blockIdx.z == 0) ? bq : (blockIdx.z == 1) ? bk : bv;
    unsigned*    C     = (blockIdx.z == 0) ? q  : (blockIdx.z == 1) ? k  : v;
    gemm_body<false, false, true, true, false>(A, B, bias, nullptr, C,
                                               ROWS, D_MODEL, D_MODEL, D_MODEL,
                                               blockIdx.x, blockIdx.y, 0, D_MODEL);
}

// ---------------- tensor-core causal attention (128-row Q tiles, tf32 mma) ----------------
// Q staged once in MMA-fragment order (1 LDS.128/frag); K stored as (k,k+4) uint2 pairs
// with row stride 36 uint2 (phase-conflict-free LDS.64); V k-major [64][68]; P [128][68].
#define QF_WORDS (8 * 8 * 32 * 4)            // 8192
#define KP_WORDS (64 * 36 * 2)               // 4608
#define VS_WORDS (64 * 68)                   // 4352
#define PS_WORDS (128 * 68)                  // 8704
#define ATT_SMEM ((QF_WORDS + KP_WORDS + VS_WORDS + PS_WORDS) * 4)
__global__ __launch_bounds__(256, 1)
void attn_kernel(const unsigned* __restrict__ q, const unsigned* __restrict__ k,
                 const unsigned* __restrict__ v, unsigned* __restrict__ o) {
    extern __shared__ unsigned smu[];
    unsigned* Qf = smu;                    // fragment-order Q
    unsigned* Kp = Qf + QF_WORDS;          // K pairs
    unsigned* Vs = Kp + KP_WORDS;          // V k-major
    unsigned* Ps = Vs + VS_WORDS;          // P rows
    int qi = blockIdx.x, hh = blockIdx.y, b = blockIdx.z;
    int tid = threadIdx.x, lane = tid & 31, warp = tid >> 5;
    int lr = lane >> 2, lc = lane & 3;
    int lane_s = lr * 4 + (lc ^ ((lr >> 1) & 3));
    const size_t base = ((size_t)b * SEQ) * D_MODEL + (size_t)hh * HEAD_DIM;
    const float inv_scale = 0.03608439182435161f;   // 1/sqrt(768)

    // stage Q tile in fragment order
#pragma unroll
    for (int i = 0; i < 8; i++) {
        int id = tid + 256 * i;
        int r = id >> 4, ch = id & 15;
        uint4 qv = *(const uint4*)(q + base + (size_t)(qi * 128 + r) * D_MODEL + ch * 4);
        int wq = r >> 4, lrq = r & 15;
        int qlr = lrq & 7, qhi = lrq >> 3;
        int ks = ch >> 1, half = ch & 1;
        int slot = qhi + 2 * half;
        int qsw = (qlr >> 1) & 3;
        unsigned* qb = Qf + ((wq * 8 + ks) * 32) * 4;
        unsigned vals[4] = {qv.x, qv.y, qv.z, qv.w};
#pragma unroll
        for (int j = 0; j < 4; j++)
            qb[(qlr * 4 + (j ^ qsw)) * 4 + slot] = vals[j];
    }

    // prefetch K/V tile j=0
    int str = tid >> 4, sch = tid & 15;       // staging row base, chunk
    int se4 = sch * 4;
    int sks = se4 >> 3, shalf = (se4 >> 2) & 1;
    uint4 kr[4], vr[4];
#pragma unroll
    for (int i = 0; i < 4; i++) {
        int r = str + 16 * i;
        size_t goff = base + (size_t)r * D_MODEL + se4;
        kr[i] = *(const uint4*)(k + goff);
        vr[i] = *(const uint4*)(v + goff);
    }

    float m_[2], l_[2], oacc[8][4];
    m_[0] = m_[1] = -1e30f; l_[0] = l_[1] = 0.f;
#pragma unroll
    for (int ni = 0; ni < 8; ni++)
#pragma unroll
        for (int r = 0; r < 4; r++) oacc[ni][r] = 0.f;

    unsigned* Prow0 = Ps + (warp * 16 + lr) * 68;
    unsigned* Prow1 = Prow0 + 8 * 68;

    int jmax = 2 * qi + 1;
    for (int j = 0; j <= jmax; j++) {
        __syncthreads();
#pragma unroll
        for (int i = 0; i < 4; i++) {
            int r = str + 16 * i;
            // K pairs: word = (r*36 + sks*4 + j)*2 + shalf
            unsigned* kpb = Kp + (r * 36 + sks * 4) * 2 + shalf;
            kpb[0] = kr[i].x; kpb[2] = kr[i].y; kpb[4] = kr[i].z; kpb[6] = kr[i].w;
            *(uint4*)&Vs[r * 68 + se4] = vr[i];
        }
        if (j < jmax) {
#pragma unroll
            for (int i = 0; i < 4; i++) {
                int r = str + 16 * i;
                size_t goff = base + (size_t)((j + 1) * 64 + r) * D_MODEL + se4;
                kr[i] = *(const uint4*)(k + goff);
                vr[i] = *(const uint4*)(v + goff);
            }
        }
        __syncthreads();

        // ---- S = Q K^T ----
        float s[8][4];
#pragma unroll
        for (int ni = 0; ni < 8; ni++)
#pragma unroll
            for (int r = 0; r < 4; r++) s[ni][r] = 0.f;

#pragma unroll
        for (int ks = 0; ks < 8; ks++) {
            unsigned a[4];
            uint4 fa = *(const uint4*)(Qf + ((warp * 8 + ks) * 32 + lane_s) * 4);
            a[0] = fa.x; a[1] = fa.y; a[2] = fa.z; a[3] = fa.w;
#pragma unroll
            for (int ni = 0; ni < 8; ni++) {
                uint2 kb = *(const uint2*)(Kp + ((ni * 8 + lr) * 36 + ks * 4 + lc) * 2);
                unsigned bfr[2] = {kb.x, kb.y};
                mma_tf32(s[ni], a, bfr);
            }
        }

        // ---- scale + mask + online softmax ----
#pragma unroll
        for (int half = 0; half < 2; half++) {
            int qr = qi * 128 + warp * 16 + lr + half * 8;
            float rm = -1e30f;
#pragma unroll
            for (int ni = 0; ni < 8; ni++)
#pragma unroll
                for (int cc = 0; cc < 2; cc++) {
                    float val = s[ni][half * 2 + cc] * inv_scale;
                    int col = j * 64 + ni * 8 + lc * 2 + cc;
                    if (col > qr) val = -1e30f;
                    s[ni][half * 2 + cc] = val;
                    rm = fmaxf(rm, val);
                }
            rm = fmaxf(rm, __shfl_xor_sync(0xffffffffu, rm, 1));
            rm = fmaxf(rm, __shfl_xor_sync(0xffffffffu, rm, 2));
            float mnew = fmaxf(m_[half], rm);
            float alpha = __expf(m_[half] - mnew);
            float psum = 0.f;
#pragma unroll
            for (int ni = 0; ni < 8; ni++)
#pragma unroll
                for (int cc = 0; cc < 2; cc++) {
                    float p = __expf(s[ni][half * 2 + cc] - mnew);
                    s[ni][half * 2 + cc] = p;
                    psum += p;
                }
            psum += __shfl_xor_sync(0xffffffffu, psum, 1);
            psum += __shfl_xor_sync(0xffffffffu, psum, 2);
            l_[half] = l_[half] * alpha + psum;
            m_[half] = mnew;
#pragma unroll
            for (int ni = 0; ni < 8; ni++) {
                oacc[ni][half * 2 + 0] *= alpha;
                oacc[ni][half * 2 + 1] *= alpha;
            }
        }

        // ---- store P (tf32) warp-local ----
#pragma unroll
        for (int ni = 0; ni < 8; ni++) {
            Prow0[ni * 8 + lc * 2]     = f2tf(s[ni][0]);
            Prow0[ni * 8 + lc * 2 + 1] = f2tf(s[ni][1]);
            Prow1[ni * 8 + lc * 2]     = f2tf(s[ni][2]);
            Prow1[ni * 8 + lc * 2 + 1] = f2tf(s[ni][3]);
        }
        __syncwarp();

        // ---- O += P V ----
#pragma unroll
        for (int ks = 0; ks < 8; ks++) {
            int poff = ks * 8 + lc;
            unsigned a[4];
            a[0] = Prow0[poff];
            a[1] = Prow1[poff];
            a[2] = Prow0[poff + 4];
            a[3] = Prow1[poff + 4];
#pragma unroll
            for (int ni = 0; ni < 8; ni++) {
                unsigned bfr[2];
                bfr[0] = Vs[(ks * 8 + lc) * 68 + ni * 8 + lr];
                bfr[1] = Vs[(ks * 8 + lc + 4) * 68 + ni * 8 + lr];
                mma_tf32(oacc[ni], a, bfr);
            }
        }
    }

    float inv0 = 1.0f / l_[0], inv1 = 1.0f / l_[1];
    int row0 = qi * 128 + warp * 16 + lr;
#pragma unroll
    for (int ni = 0; ni < 8; ni++) {
        int col = ni * 8 + lc * 2;
        unsigned* p0 = o + base + (size_t)row0 * D_MODEL + col;
        unsigned* p1 = o + base + (size_t)(row0 + 8) * D_MODEL + col;
        p0[0] = f2tf(oacc[ni][0] * inv0);
        p0[1] = f2tf(oacc[ni][1] * inv0);
        p1[0] = f2tf(oacc[ni][2] * inv1);
        p1[1] = f2tf(oacc[ni][3] * inv1);
    }
}

// ---------------- launch ----------------
extern "C" void kernel_launch(void* const* d_in, const int* in_sizes, int n_in,
                              void* d_out, int out_size) {
    const int*   x      = (const int*)  d_in[0];
    const float* wte    = (const float*)d_in[1];
    const float* wpe    = (const float*)d_in[2];
    const float* ln1_w  = (const float*)d_in[3];
    const float* ln1_b  = (const float*)d_in[4];
    const float* Wq     = (const float*)d_in[5];
    const float* bq     = (const float*)d_in[6];
    const float* Wk     = (const float*)d_in[7];
    const float* bk     = (const float*)d_in[8];
    const float* Wv     = (const float*)d_in[9];
    const float* bv     = (const float*)d_in[10];
    const float* Wp     = (const float*)d_in[11];
    const float* bp     = (const float*)d_in[12];
    const float* ln2_w  = (const float*)d_in[13];
    const float* ln2_b  = (const float*)d_in[14];
    const float* lnfc_w = (const float*)d_in[15];
    const float* lnfc_b = (const float*)d_in[16];
    const float* W1     = (const float*)d_in[17];
    const float* b1     = (const float*)d_in[18];
    const float* W2     = (const float*)d_in[19];
    const float* b2     = (const float*)d_in[20];
    const float* lnf_w  = (const float*)d_in[21];
    const float* lnf_b  = (const float*)d_in[22];
    const float* Wh     = (const float*)d_in[23];
    const float* bh     = (const float*)d_in[24];
    float* out = (float*)d_out;

    float *h, *part;
    unsigned *a, *q, *k, *v, *o, *m, *whp, *wq, *wk, *wv, *wp, *w1, *w2;
    cudaGetSymbolAddress((void**)&h, g_h);
    cudaGetSymbolAddress((void**)&a, g_a);
    cudaGetSymbolAddress((void**)&q, g_q);
    cudaGetSymbolAddress((void**)&k, g_k);
    cudaGetSymbolAddress((void**)&v, g_v);
    cudaGetSymbolAddress((void**)&o, g_o);
    cudaGetSymbolAddress((void**)&m, g_m);
    cudaGetSymbolAddress((void**)&part, g_part);
    cudaGetSymbolAddress((void**)&whp, g_whp);
    cudaGetSymbolAddress((void**)&wq, g_wq);
    cudaGetSymbolAddress((void**)&wk, g_wk);
    cudaGetSymbolAddress((void**)&wv, g_wv);
    cudaGetSymbolAddress((void**)&wp, g_wp);
    cudaGetSymbolAddress((void**)&w1, g_w1);
    cudaGetSymbolAddress((void**)&w2, g_w2);

    cudaFuncSetAttribute(attn_kernel, cudaFuncAttributeMaxDynamicSharedMemorySize, ATT_SMEM);
    cudaFuncSetAttribute(qkv_kernel, cudaFuncAttributeMaxDynamicSharedMemorySize, GEMM_SMEM);
    cudaFuncSetAttribute(gemm_kernel<true, false, false, true, false>,
                         cudaFuncAttributeMaxDynamicSharedMemorySize, GEMM_SMEM);   // FF1
    cudaFuncSetAttribute(gemm_kernel<false, false, false, false, false>,
                         cudaFuncAttributeMaxDynamicSharedMemorySize, GEMM_SMEM);   // head
    cudaFuncSetAttribute(gemm_kernel<false, false, false, false, true>,
                         cudaFuncAttributeMaxDynamicSharedMemorySize, GEMM_SMEM);   // split-K

    // one-time conversions
    int nW  = N_LAYERS * WSZ / 4;
    int nW4 = N_LAYERS * WSZ;
    cvt_kernel<<<(nW + 255) / 256, 256>>>(Wq, wq, nW);
    cvt_kernel<<<(nW + 255) / 256, 256>>>(Wk, wk, nW);
    cvt_kernel<<<(nW + 255) / 256, 256>>>(Wv, wv, nW);
    cvt_kernel<<<(nW + 255) / 256, 256>>>(Wp, wp, nW);
    cvt_kernel<<<(nW4 + 255) / 256, 256>>>(W1, w1, nW4);
    cvt_kernel<<<(nW4 + 255) / 256, 256>>>(W2, w2, nW4);
    pad_wh_kernel<<<dim3((VOCAB_P + 255) / 256, D_MODEL), 256>>>(Wh, whp);

    embed_kernel<<<ROWS, 256>>>(x, wte, wpe, h);

    dim3 gQKV(D_MODEL / 256, ROWS / 128, 3);          // (3, 32, 3)
    dim3 gSplit(D_MODEL / 256, ROWS / 128, 3);        // (3, 32, 3) split-K
    dim3 gFF1(D_FF / 256, ROWS / 128);                // (12, 32)
    dim3 gHead(VOCAB_P / 256, ROWS / 128);            // (197, 32)
    dim3 gAttn(SEQ / 128, N_HEADS, BATCH);            // (8, 12, 4)

    // layer 0 ln1 (no preceding partials)
    ln_kernel<false><<<ROWS, 256>>>(h, ln1_w, ln1_b, nullptr, nullptr, a);

    for (int l = 0; l < N_LAYERS; l++) {
        const unsigned* wq_l = wq + (size_t)l * WSZ;
        const unsigned* wk_l = wk + (size_t)l * WSZ;
        const unsigned* wv_l = wv + (size_t)l * WSZ;
        const unsigned* wp_l = wp + (size_t)l * WSZ;
        const unsigned* w1_l = w1 + (size_t)l * WSZ * 4;
        const unsigned* w2_l = w2 + (size_t)l * WSZ * 4;

        qkv_kernel<<<gQKV, 256, GEMM_SMEM>>>(a, wq_l, wk_l, wv_l,
                                             bq + l * D_MODEL, bk + l * D_MODEL, bv + l * D_MODEL,
                                             q, k, v);

        attn_kernel<<<gAttn, 256, ATT_SMEM>>>(q, k, v, o);

        // proj: split-K x3 (K=768 -> 256 each), then fused reduce + ln2∘lnfc
        gemm_kernel<false, false, false, false, true><<<gSplit, 256, GEMM_SMEM>>>(
            o, wp_l, nullptr, nullptr, part, ROWS, D_MODEL, D_MODEL, D_MODEL, 256);
        lnred_kernel<true><<<ROWS, 256>>>(part, bp + l * D_MODEL, h,
                                          ln2_w + l * D_MODEL, ln2_b + l * D_MODEL,
                                          lnfc_w + l * D_MODEL, lnfc_b + l * D_MODEL, a);

        gemm_kernel<true, false, false, true, false><<<gFF1, 256, GEMM_SMEM>>>(
            a, w1_l, b1 + l * D_FF, nullptr, m, ROWS, D_FF, D_MODEL, D_FF, D_MODEL);

        // FF2: split-K x3 (K=3072 -> 1024 each), then fused reduce + next ln1 (or lnf)
        gemm_kernel<false, false, false, false, true><<<gSplit, 256, GEMM_SMEM>>>(
            m, w2_l, nullptr, nullptr, part, ROWS, D_MODEL, D_FF, D_MODEL, 1024);
        if (l + 1 < N_LAYERS) {
            lnred_kernel<false><<<ROWS, 256>>>(part, b2 + l * D_MODEL, h,
                                               ln1_w + (l + 1) * D_MODEL,
                                               ln1_b + (l + 1) * D_MODEL,
                                               nullptr, nullptr, a);
        } else {
            lnred_kernel<false><<<ROWS, 256>>>(part, b2 + l * D_MODEL, h,
                                               lnf_w, lnf_b, nullptr, nullptr, a);
        }
    }

    gemm_kernel<false, false, false, false, false><<<gHead, 256, GEMM_SMEM>>>(
        a, whp, bh, nullptr, out, ROWS, VOCAB_P, D_MODEL, VOCAB, D_MODEL);
}

// round 13
// speedup vs baseline: 3.2434x; 1.4650x over previous
#include <cuda_runtime.h>
#include <cuda_fp16.h>
#include <math.h>

#define D_MODEL 768
#define N_HEADS 12
#define HEAD_DIM 64
#define N_LAYERS 12
#define SEQ 1024
#define BATCH 4
#define ROWS (BATCH * SEQ)       // 4096
#define D_FF (4 * D_MODEL)       // 3072
#define VOCAB 50257
#define VOCAB_P 50432            // padded to multiple of 256
#define WSZ (D_MODEL * D_MODEL)  // 589824

// fp16 GEMM smem: Asf 2*8*2*32*4 = 4096 words, Bs 2*16*264 = 8448 words
#define ASF_WORDS (2 * 8 * 2 * 32 * 4)
#define BS_WORDS  (2 * 16 * 264)
#define GEMM_SMEM ((ASF_WORDS + BS_WORDS) * 4)   // 50176 bytes

// ---------------- scratch (device globals; no allocation allowed) ----------------
__device__ float    g_h[ROWS * D_MODEL];
__device__ __half   g_a[ROWS * D_MODEL];     // fp16 activations (LN out)
__device__ unsigned g_q[ROWS * D_MODEL];     // tf32 q (attention)
__device__ unsigned g_k[ROWS * D_MODEL];
__device__ unsigned g_v[ROWS * D_MODEL];
__device__ __half   g_o[ROWS * D_MODEL];     // fp16 attn out
__device__ __half   g_m[ROWS * D_FF];        // fp16 FF1 out
__device__ float    g_part[3 * ROWS * D_MODEL];  // split-K partials
// fp16 pre-packed weights (half2 along K: word[k2][n] = (W[2k2][n], W[2k2+1][n]))
__device__ unsigned g_wq[N_LAYERS * WSZ / 2];
__device__ unsigned g_wk[N_LAYERS * WSZ / 2];
__device__ unsigned g_wv[N_LAYERS * WSZ / 2];
__device__ unsigned g_wp[N_LAYERS * WSZ / 2];
__device__ unsigned g_w1[N_LAYERS * WSZ * 2];
__device__ unsigned g_w2[N_LAYERS * WSZ * 2];
__device__ unsigned g_whp[(D_MODEL / 2) * VOCAB_P];

// ---------------- helpers ----------------
__device__ __forceinline__ unsigned f2tf(float x) {
    unsigned r;
    asm("cvt.rna.tf32.f32 %0, %1;" : "=r"(r) : "f"(x));
    return r;
}

__device__ __forceinline__ unsigned packh2(float lo, float hi) {
    __half2 t = __floats2half2_rn(lo, hi);
    return *reinterpret_cast<unsigned*>(&t);
}

__device__ __forceinline__ void mma_tf32(float* c, const unsigned* a, const unsigned* b) {
    asm volatile(
        "mma.sync.aligned.m16n8k8.row.col.f32.tf32.tf32.f32 "
        "{%0,%1,%2,%3}, {%4,%5,%6,%7}, {%8,%9}, {%0,%1,%2,%3};"
        : "+f"(c[0]), "+f"(c[1]), "+f"(c[2]), "+f"(c[3])
        : "r"(a[0]), "r"(a[1]), "r"(a[2]), "r"(a[3]), "r"(b[0]), "r"(b[1]));
}

__device__ __forceinline__ void mma_f16(float* c, const unsigned* a, const unsigned* b) {
    asm volatile(
        "mma.sync.aligned.m16n8k16.row.col.f32.f16.f16.f32 "
        "{%0,%1,%2,%3}, {%4,%5,%6,%7}, {%8,%9}, {%0,%1,%2,%3};"
        : "+f"(c[0]), "+f"(c[1]), "+f"(c[2]), "+f"(c[3])
        : "r"(a[0]), "r"(a[1]), "r"(a[2]), "r"(a[3]), "r"(b[0]), "r"(b[1]));
}

__device__ __forceinline__ void cp16(unsigned saddr, const unsigned* gptr) {
    asm volatile("cp.async.cg.shared.global [%0], [%1], 16;"
                 :: "r"(saddr), "l"(gptr) : "memory");
}

// ---------------- weight packing: fp32 [rows][N] -> half2 words [rows/2][N] ----------------
__global__ void pack_kernel(const float* __restrict__ src, unsigned* __restrict__ dst,
                            int rows2, int n4) {
    int i = blockIdx.x * 256 + threadIdx.x;
    if (i < rows2 * n4) {
        int r2 = i / n4, c = i % n4;
        size_t N = (size_t)n4 * 4;
        float4 a = *(const float4*)(src + (size_t)(2 * r2) * N + c * 4);
        float4 b = *(const float4*)(src + (size_t)(2 * r2 + 1) * N + c * 4);
        uint4 u;
        u.x = packh2(a.x, b.x); u.y = packh2(a.y, b.y);
        u.z = packh2(a.z, b.z); u.w = packh2(a.w, b.w);
        ((uint4*)dst)[i] = u;
    }
}

// headed qkv weights: [B=L*H][K][64] -> [B][K/2][64] half2 words
__global__ void pack_headed_kernel(const float* __restrict__ src, unsigned* __restrict__ dst,
                                   int nblocks, int K) {
    int i = blockIdx.x * 256 + threadIdx.x;
    int per = (K / 2) * 16;
    if (i < nblocks * per) {
        int b = i / per, rem = i % per;
        int r2 = rem / 16, c = rem % 16;
        const float* s0 = src + ((size_t)b * K + 2 * r2) * 64 + c * 4;
        float4 a = *(const float4*)(s0);
        float4 bb = *(const float4*)(s0 + 64);
        uint4 u;
        u.x = packh2(a.x, bb.x); u.y = packh2(a.y, bb.y);
        u.z = packh2(a.z, bb.z); u.w = packh2(a.w, bb.w);
        ((uint4*)dst)[i] = u;
    }
}

// LM head: [K][VOCAB] -> [K/2][VOCAB_P] half2 words, zero-padded
__global__ void pad_wh_kernel(const float* __restrict__ Wh, unsigned* __restrict__ WhP) {
    int r2 = blockIdx.y;
    int col = blockIdx.x * 256 + threadIdx.x;
    if (col < VOCAB_P) {
        float lo = 0.f, hi = 0.f;
        if (col < VOCAB) {
            lo = Wh[(size_t)(2 * r2) * VOCAB + col];
            hi = Wh[(size_t)(2 * r2 + 1) * VOCAB + col];
        }
        WhP[(size_t)r2 * VOCAB_P + col] = packh2(lo, hi);
    }
}

// ---------------- embedding ----------------
__global__ void embed_kernel(const int* __restrict__ x, const float* __restrict__ wte,
                             const float* __restrict__ wpe, float* __restrict__ h) {
    int row = blockIdx.x;
    int tok = x[row];
    int s = row & (SEQ - 1);
    const float* te = wte + (size_t)tok * D_MODEL;
    const float* pe = wpe + (size_t)s * D_MODEL;
    float* out = h + (size_t)row * D_MODEL;
    for (int d = threadIdx.x; d < D_MODEL; d += 256)
        out[d] = te[d] + pe[d];
}

// ---------------- LN core ----------------
template <bool DOUBLE>
__device__ __forceinline__
void ln_core(float v0, float v1, float v2,
             const float* __restrict__ w1, const float* __restrict__ b1,
             const float* __restrict__ w2, const float* __restrict__ b2,
             __half* __restrict__ yr, float* red, int tid) {
    red[tid] = v0 + v1 + v2;
    __syncthreads();
    for (int s = 128; s > 0; s >>= 1) { if (tid < s) red[tid] += red[tid + s]; __syncthreads(); }
    float mean = red[0] * (1.0f / D_MODEL);
    __syncthreads();
    float d0 = v0 - mean, d1 = v1 - mean, d2 = v2 - mean;
    red[tid] = d0 * d0 + d1 * d1 + d2 * d2;
    __syncthreads();
    for (int s = 128; s > 0; s >>= 1) { if (tid < s) red[tid] += red[tid + s]; __syncthreads(); }
    float rstd = rsqrtf(red[0] * (1.0f / D_MODEL) + 1e-5f);
    float y0 = d0 * rstd * w1[tid]       + b1[tid];
    float y1 = d1 * rstd * w1[tid + 256] + b1[tid + 256];
    float y2 = d2 * rstd * w1[tid + 512] + b1[tid + 512];

    if (DOUBLE) {
        __syncthreads();
        red[tid] = y0 + y1 + y2;
        __syncthreads();
        for (int s = 128; s > 0; s >>= 1) { if (tid < s) red[tid] += red[tid + s]; __syncthreads(); }
        float mean2 = red[0] * (1.0f / D_MODEL);
        __syncthreads();
        float e0 = y0 - mean2, e1 = y1 - mean2, e2 = y2 - mean2;
        red[tid] = e0 * e0 + e1 * e1 + e2 * e2;
        __syncthreads();
        for (int s = 128; s > 0; s >>= 1) { if (tid < s) red[tid] += red[tid + s]; __syncthreads(); }
        float rstd2 = rsqrtf(red[0] * (1.0f / D_MODEL) + 1e-5f);
        y0 = e0 * rstd2 * w2[tid]       + b2[tid];
        y1 = e1 * rstd2 * w2[tid + 256] + b2[tid + 256];
        y2 = e2 * rstd2 * w2[tid + 512] + b2[tid + 512];
    }
    yr[tid]       = __float2half_rn(y0);
    yr[tid + 256] = __float2half_rn(y1);
    yr[tid + 512] = __float2half_rn(y2);
}

template <bool DOUBLE>
__global__ void ln_kernel(const float* __restrict__ x,
                          const float* __restrict__ w1, const float* __restrict__ b1,
                          const float* __restrict__ w2, const float* __restrict__ b2,
                          __half* __restrict__ y) {
    __shared__ float red[256];
    int row = blockIdx.x, tid = threadIdx.x;
    const float* xr = x + (size_t)row * D_MODEL;
    ln_core<DOUBLE>(xr[tid], xr[tid + 256], xr[tid + 512],
                    w1, b1, w2, b2, y + (size_t)row * D_MODEL, red, tid);
}

// fused split-K reduce + residual + LN
template <bool DOUBLE>
__global__ void lnred_kernel(const float* __restrict__ part, const float* __restrict__ bias,
                             float* __restrict__ h,
                             const float* __restrict__ w1, const float* __restrict__ b1,
                             const float* __restrict__ w2, const float* __restrict__ b2,
                             __half* __restrict__ y) {
    __shared__ float red[256];
    int row = blockIdx.x, tid = threadIdx.x;
    float v[3];
#pragma unroll
    for (int i = 0; i < 3; i++) {
        int c = tid + i * 256;
        size_t idx = (size_t)row * D_MODEL + c;
        v[i] = part[idx] + part[idx + (size_t)ROWS * D_MODEL]
             + part[idx + 2 * (size_t)ROWS * D_MODEL] + bias[c] + h[idx];
        h[idx] = v[i];
    }
    ln_core<DOUBLE>(v[0], v[1], v[2], w1, b1, w2, b2,
                    y + (size_t)row * D_MODEL, red, tid);
}

// ---------------- FP16 tensor-core GEMM body (128x256 tile, BK=32) ----------------
// 8 warps, warp tile 64x64 (4 mi x 8 ni m16n8k16). A: fp16 [M][K] (read as half2 words).
// B: half2-packed words [K/2][N], or HEADED [H][K/2][64]. Output: fp32 / fp16 / tf32-bits.
template <bool GELU, bool RESID, bool HEADED, bool OUTTF, bool OUTH, bool PARTIAL>
__device__ __forceinline__
void gemm_body(const unsigned* __restrict__ A, const unsigned* __restrict__ B,
               const float* __restrict__ bias, const float* __restrict__ resid,
               void* __restrict__ Cv, int M, int N, int K, int NC,
               int bn, int bm, int kOff, int kLen) {
    extern __shared__ unsigned smu[];
    unsigned* Asf = smu;                  // [2][8 mi][2 ks][32][4]
    unsigned* Bsm = smu + ASF_WORDS;      // [2][16 k2][264]
    int tid = threadIdx.x;
    int lane = tid & 31, warp = tid >> 5;
    int wm = (warp & 1) * 64;
    int wn = (warp >> 1) * 64;
    int lr = lane >> 2;
    int lc = lane & 3;
    int lane_s = lr * 4 + (lc ^ ((lr >> 1) & 3));
    int K2 = K >> 1;

    float acc[4][8][4];
#pragma unroll
    for (int mi = 0; mi < 4; mi++)
#pragma unroll
        for (int ni = 0; ni < 8; ni++)
#pragma unroll
            for (int r = 0; r < 4; r++) acc[mi][ni][r] = 0.f;

    int arow_l = tid >> 1;
    int aks    = tid & 1;                  // ks half this thread stages
    int akw    = aks * 8;                  // word offset within BK/2=16 words
    int ami    = arow_l >> 4;
    int alr    = arow_l & 7;
    int ahi    = (arow_l >> 3) & 1;
    int asw    = (alr >> 1) & 3;
    int bkr    = tid >> 4;                 // 0..15 (k2 row)
    int bcl    = (tid & 15) * 4;           // word col within 64-chunk

    const unsigned* aptr = A + (size_t)(bm * 128 + arow_l) * K2 + (kOff >> 1) + akw;
    const unsigned* bptr[4];
    int strideB;
    if (HEADED) {
        strideB = 64;
#pragma unroll
        for (int c = 0; c < 4; c++)
            bptr[c] = B + ((size_t)(bn * 4 + c) * K2 + (kOff >> 1) + bkr) * 64 + bcl;
    } else {
        strideB = N;
#pragma unroll
        for (int c = 0; c < 4; c++)
            bptr[c] = B + (size_t)((kOff >> 1) + bkr) * N + bn * 256 + c * 64 + bcl;
    }
    unsigned bsbase = (unsigned)__cvta_generic_to_shared(Bsm) + (bkr * 264 + bcl) * 4;

    uint4 a0, a1;
    auto loadA = [&](int k0) {
        const unsigned* ap = aptr + (k0 >> 1);
        a0 = *(const uint4*)(ap);
        a1 = *(const uint4*)(ap + 4);
    };
    auto storeA = [&](int buf) {
        unsigned ar[8] = {a0.x, a0.y, a0.z, a0.w, a1.x, a1.y, a1.z, a1.w};
        unsigned* abase = Asf + (((buf * 8 + ami) * 2 + aks) * 32) * 4;
#pragma unroll
        for (int j = 0; j < 8; j++) {
            int ls   = alr * 4 + ((j & 3) ^ asw);
            int slot = ahi + 2 * (j >> 2);
            abase[ls * 4 + slot] = ar[j];
        }
    };
    auto stageB = [&](int k0, int buf) {
#pragma unroll
        for (int c = 0; c < 4; c++)
            cp16(bsbase + buf * 16 * 264 * 4 + c * 64 * 4,
                 bptr[c] + (size_t)(k0 >> 1) * strideB);
        asm volatile("cp.async.commit_group;" ::: "memory");
    };

    stageB(0, 0);
    loadA(0);
    storeA(0);
    asm volatile("cp.async.wait_all;" ::: "memory");
    __syncthreads();

    int cur = 0;
    for (int k0 = 0; k0 < kLen; k0 += 32) {
        bool has_next = (k0 + 32) < kLen;
        if (has_next) {
            stageB(k0 + 32, cur ^ 1);
            loadA(k0 + 32);
        }

#pragma unroll
        for (int ks = 0; ks < 2; ks++) {
            unsigned afr[4][4], bfr[8][2];
#pragma unroll
            for (int mi = 0; mi < 4; mi++) {
                int mig = (warp & 1) * 4 + mi;
                uint4 fa = *(const uint4*)(Asf + (((cur * 8 + mig) * 2 + ks) * 32 + lane_s) * 4);
                afr[mi][0] = fa.x; afr[mi][1] = fa.y;
                afr[mi][2] = fa.z; afr[mi][3] = fa.w;
            }
#pragma unroll
            for (int ni = 0; ni < 8; ni++) {
                int n0 = wn + ni * 8;
                bfr[ni][0] = Bsm[(cur * 16 + ks * 8 + lc) * 264 + n0 + lr];
                bfr[ni][1] = Bsm[(cur * 16 + ks * 8 + lc + 4) * 264 + n0 + lr];
            }
#pragma unroll
            for (int mi = 0; mi < 4; mi++)
#pragma unroll
                for (int ni = 0; ni < 8; ni++)
                    mma_f16(acc[mi][ni], afr[mi], bfr[ni]);
        }

        if (has_next) storeA(cur ^ 1);
        asm volatile("cp.async.wait_all;" ::: "memory");
        __syncthreads();
        cur ^= 1;
    }

    float*    Cf = (float*)Cv;
    unsigned* Cu = (unsigned*)Cv;
    __half*   Ch = (__half*)Cv;
#pragma unroll
    for (int mi = 0; mi < 4; mi++) {
        int row0 = bm * 128 + wm + mi * 16 + lr;
#pragma unroll
        for (int ni = 0; ni < 8; ni++) {
            int col = bn * 256 + wn + ni * 8 + lc * 2;
#pragma unroll
            for (int half = 0; half < 2; half++) {
                int row = row0 + half * 8;
                if (OUTH) {
                    float v0 = acc[mi][ni][half * 2 + 0] + bias[col];
                    float v1 = acc[mi][ni][half * 2 + 1] + bias[col + 1];
                    if (GELU) {
                        v0 = 0.5f * v0 * (1.0f + erff(v0 * 0.70710678118654752f));
                        v1 = 0.5f * v1 * (1.0f + erff(v1 * 0.70710678118654752f));
                    }
                    __half2 hv = __floats2half2_rn(v0, v1);
                    *(__half2*)(Ch + (size_t)row * NC + col) = hv;
                } else {
#pragma unroll
                    for (int cc = 0; cc < 2; cc++) {
                        int c = col + cc;
                        if (c < NC) {
                            float val = acc[mi][ni][half * 2 + cc];
                            if (PARTIAL) {
                                Cf[(size_t)row * NC + c] = val;
                            } else {
                                val += bias[c];
                                if (GELU) val = 0.5f * val * (1.0f + erff(val * 0.70710678118654752f));
                                if (RESID) val += resid[(size_t)row * NC + c];
                                if (OUTTF) Cu[(size_t)row * NC + c] = f2tf(val);
                                else       Cf[(size_t)row * NC + c] = val;
                            }
                        }
                    }
                }
            }
        }
    }
}

template <bool GELU, bool RESID, bool HEADED, bool OUTTF, bool OUTH, bool PARTIAL>
__global__ __launch_bounds__(256, 1)
void gemm_kernel(const unsigned* __restrict__ A, const unsigned* __restrict__ B,
                 const float* __restrict__ bias, const float* __restrict__ resid,
                 void* __restrict__ C, int M, int N, int K, int NC, int kLen) {
    void* Cv = C;
    int kOff = 0;
    if (PARTIAL) {
        kOff = blockIdx.z * kLen;
        Cv = (float*)C + (size_t)blockIdx.z * M * NC;
    }
    gemm_body<GELU, RESID, HEADED, OUTTF, OUTH, PARTIAL>(A, B, bias, resid, Cv, M, N, K, NC,
                                                         blockIdx.x, blockIdx.y, kOff, kLen);
}

// Fused Q/K/V projection: fp16 inputs, tf32-bit outputs for the attention kernel.
__global__ __launch_bounds__(256, 1)
void qkv_kernel(const unsigned* __restrict__ A,
                const unsigned* __restrict__ Wq, const unsigned* __restrict__ Wk,
                const unsigned* __restrict__ Wv,
                const float* __restrict__ bq, const float* __restrict__ bk,
                const float* __restrict__ bv,
                unsigned* __restrict__ q, unsigned* __restrict__ k, unsigned* __restrict__ v) {
    const unsigned* B  = (blockIdx.z == 0) ? Wq : (blockIdx.z == 1) ? Wk : Wv;
    const float* bias  = (blockIdx.z == 0) ? bq : (blockIdx.z == 1) ? bk : bv;
    unsigned*    C     = (blockIdx.z == 0) ? q  : (blockIdx.z == 1) ? k  : v;
    gemm_body<false, false, true, true, false, false>(A, B, bias, nullptr, C,
                                                      ROWS, D_MODEL, D_MODEL, D_MODEL,
                                                      blockIdx.x, blockIdx.y, 0, D_MODEL);
}

// ---------------- tensor-core causal attention (128-row Q tiles, tf32 mma) ----------------
#define QF_WORDS (8 * 8 * 32 * 4)            // 8192
#define KP_WORDS (64 * 36 * 2)               // 4608
#define VS_WORDS (64 * 68)                   // 4352
#define PS_WORDS (128 * 68)                  // 8704
#define ATT_SMEM ((QF_WORDS + KP_WORDS + VS_WORDS + PS_WORDS) * 4)
__global__ __launch_bounds__(256, 1)
void attn_kernel(const unsigned* __restrict__ q, const unsigned* __restrict__ k,
                 const unsigned* __restrict__ v, __half* __restrict__ o) {
    extern __shared__ unsigned smu[];
    unsigned* Qf = smu;
    unsigned* Kp = Qf + QF_WORDS;
    unsigned* Vs = Kp + KP_WORDS;
    unsigned* Ps = Vs + VS_WORDS;
    int qi = blockIdx.x, hh = blockIdx.y, b = blockIdx.z;
    int tid = threadIdx.x, lane = tid & 31, warp = tid >> 5;
    int lr = lane >> 2, lc = lane & 3;
    int lane_s = lr * 4 + (lc ^ ((lr >> 1) & 3));
    const size_t base = ((size_t)b * SEQ) * D_MODEL + (size_t)hh * HEAD_DIM;
    const float inv_scale = 0.03608439182435161f;   // 1/sqrt(768)

    // stage Q tile in fragment order
#pragma unroll
    for (int i = 0; i < 8; i++) {
        int id = tid + 256 * i;
        int r = id >> 4, ch = id & 15;
        uint4 qv = *(const uint4*)(q + base + (size_t)(qi * 128 + r) * D_MODEL + ch * 4);
        int wq = r >> 4, lrq = r & 15;
        int qlr = lrq & 7, qhi = lrq >> 3;
        int ks = ch >> 1, half = ch & 1;
        int slot = qhi + 2 * half;
        int qsw = (qlr >> 1) & 3;
        unsigned* qb = Qf + ((wq * 8 + ks) * 32) * 4;
        unsigned vals[4] = {qv.x, qv.y, qv.z, qv.w};
#pragma unroll
        for (int j = 0; j < 4; j++)
            qb[(qlr * 4 + (j ^ qsw)) * 4 + slot] = vals[j];
    }

    int str = tid >> 4, sch = tid & 15;
    int se4 = sch * 4;
    int sks = se4 >> 3, shalf = (se4 >> 2) & 1;
    uint4 kr[4], vr[4];
#pragma unroll
    for (int i = 0; i < 4; i++) {
        int r = str + 16 * i;
        size_t goff = base + (size_t)r * D_MODEL + se4;
        kr[i] = *(const uint4*)(k + goff);
        vr[i] = *(const uint4*)(v + goff);
    }

    float m_[2], l_[2], oacc[8][4];
    m_[0] = m_[1] = -1e30f; l_[0] = l_[1] = 0.f;
#pragma unroll
    for (int ni = 0; ni < 8; ni++)
#pragma unroll
        for (int r = 0; r < 4; r++) oacc[ni][r] = 0.f;

    unsigned* Prow0 = Ps + (warp * 16 + lr) * 68;
    unsigned* Prow1 = Prow0 + 8 * 68;

    int jmax = 2 * qi + 1;
    for (int j = 0; j <= jmax; j++) {
        __syncthreads();
#pragma unroll
        for (int i = 0; i < 4; i++) {
            int r = str + 16 * i;
            unsigned* kpb = Kp + (r * 36 + sks * 4) * 2 + shalf;
            kpb[0] = kr[i].x; kpb[2] = kr[i].y; kpb[4] = kr[i].z; kpb[6] = kr[i].w;
            *(uint4*)&Vs[r * 68 + se4] = vr[i];
        }
        if (j < jmax) {
#pragma unroll
            for (int i = 0; i < 4; i++) {
                int r = str + 16 * i;
                size_t goff = base + (size_t)((j + 1) * 64 + r) * D_MODEL + se4;
                kr[i] = *(const uint4*)(k + goff);
                vr[i] = *(const uint4*)(v + goff);
            }
        }
        __syncthreads();

        float s[8][4];
#pragma unroll
        for (int ni = 0; ni < 8; ni++)
#pragma unroll
            for (int r = 0; r < 4; r++) s[ni][r] = 0.f;

#pragma unroll
        for (int ks = 0; ks < 8; ks++) {
            unsigned a[4];
            uint4 fa = *(const uint4*)(Qf + ((warp * 8 + ks) * 32 + lane_s) * 4);
            a[0] = fa.x; a[1] = fa.y; a[2] = fa.z; a[3] = fa.w;
#pragma unroll
            for (int ni = 0; ni < 8; ni++) {
                uint2 kb = *(const uint2*)(Kp + ((ni * 8 + lr) * 36 + ks * 4 + lc) * 2);
                unsigned bfr[2] = {kb.x, kb.y};
                mma_tf32(s[ni], a, bfr);
            }
        }

#pragma unroll
        for (int half = 0; half < 2; half++) {
            int qr = qi * 128 + warp * 16 + lr + half * 8;
            float rm = -1e30f;
#pragma unroll
            for (int ni = 0; ni < 8; ni++)
#pragma unroll
                for (int cc = 0; cc < 2; cc++) {
                    float val = s[ni][half * 2 + cc] * inv_scale;
                    int col = j * 64 + ni * 8 + lc * 2 + cc;
                    if (col > qr) val = -1e30f;
                    s[ni][half * 2 + cc] = val;
                    rm = fmaxf(rm, val);
                }
            rm = fmaxf(rm, __shfl_xor_sync(0xffffffffu, rm, 1));
            rm = fmaxf(rm, __shfl_xor_sync(0xffffffffu, rm, 2));
            float mnew = fmaxf(m_[half], rm);
            float alpha = __expf(m_[half] - mnew);
            float psum = 0.f;
#pragma unroll
            for (int ni = 0; ni < 8; ni++)
#pragma unroll
                for (int cc = 0; cc < 2; cc++) {
                    float p = __expf(s[ni][half * 2 + cc] - mnew);
                    s[ni][half * 2 + cc] = p;
                    psum += p;
                }
            psum += __shfl_xor_sync(0xffffffffu, psum, 1);
            psum += __shfl_xor_sync(0xffffffffu, psum, 2);
            l_[half] = l_[half] * alpha + psum;
            m_[half] = mnew;
#pragma unroll
            for (int ni = 0; ni < 8; ni++) {
                oacc[ni][half * 2 + 0] *= alpha;
                oacc[ni][half * 2 + 1] *= alpha;
            }
        }

#pragma unroll
        for (int ni = 0; ni < 8; ni++) {
            Prow0[ni * 8 + lc * 2]     = f2tf(s[ni][0]);
            Prow0[ni * 8 + lc * 2 + 1] = f2tf(s[ni][1]);
            Prow1[ni * 8 + lc * 2]     = f2tf(s[ni][2]);
            Prow1[ni * 8 + lc * 2 + 1] = f2tf(s[ni][3]);
        }
        __syncwarp();

#pragma unroll
        for (int ks = 0; ks < 8; ks++) {
            int poff = ks * 8 + lc;
            unsigned a[4];
            a[0] = Prow0[poff];
            a[1] = Prow1[poff];
            a[2] = Prow0[poff + 4];
            a[3] = Prow1[poff + 4];
#pragma unroll
            for (int ni = 0; ni < 8; ni++) {
                unsigned bfr[2];
                bfr[0] = Vs[(ks * 8 + lc) * 68 + ni * 8 + lr];
                bfr[1] = Vs[(ks * 8 + lc + 4) * 68 + ni * 8 + lr];
                mma_tf32(oacc[ni], a, bfr);
            }
        }
    }

    float inv0 = 1.0f / l_[0], inv1 = 1.0f / l_[1];
    int row0 = qi * 128 + warp * 16 + lr;
#pragma unroll
    for (int ni = 0; ni < 8; ni++) {
        int col = ni * 8 + lc * 2;
        __half2* p0 = (__half2*)(o + base + (size_t)row0 * D_MODEL + col);
        __half2* p1 = (__half2*)(o + base + (size_t)(row0 + 8) * D_MODEL + col);
        *p0 = __floats2half2_rn(oacc[ni][0] * inv0, oacc[ni][1] * inv0);
        *p1 = __floats2half2_rn(oacc[ni][2] * inv1, oacc[ni][3] * inv1);
    }
}

// ---------------- launch ----------------
extern "C" void kernel_launch(void* const* d_in, const int* in_sizes, int n_in,
                              void* d_out, int out_size) {
    const int*   x      = (const int*)  d_in[0];
    const float* wte    = (const float*)d_in[1];
    const float* wpe    = (const float*)d_in[2];
    const float* ln1_w  = (const float*)d_in[3];
    const float* ln1_b  = (const float*)d_in[4];
    const float* Wq     = (const float*)d_in[5];
    const float* bq     = (const float*)d_in[6];
    const float* Wk     = (const float*)d_in[7];
    const float* bk     = (const float*)d_in[8];
    const float* Wv     = (const float*)d_in[9];
    const float* bv     = (const float*)d_in[10];
    const float* Wp     = (const float*)d_in[11];
    const float* bp     = (const float*)d_in[12];
    const float* ln2_w  = (const float*)d_in[13];
    const float* ln2_b  = (const float*)d_in[14];
    const float* lnfc_w = (const float*)d_in[15];
    const float* lnfc_b = (const float*)d_in[16];
    const float* W1     = (const float*)d_in[17];
    const float* b1     = (const float*)d_in[18];
    const float* W2     = (const float*)d_in[19];
    const float* b2     = (const float*)d_in[20];
    const float* lnf_w  = (const float*)d_in[21];
    const float* lnf_b  = (const float*)d_in[22];
    const float* Wh     = (const float*)d_in[23];
    const float* bh     = (const float*)d_in[24];
    float* out = (float*)d_out;

    float *h, *part;
    __half *a, *o, *m;
    unsigned *q, *k, *v, *whp, *wq, *wk, *wv, *wp, *w1, *w2;
    cudaGetSymbolAddress((void**)&h, g_h);
    cudaGetSymbolAddress((void**)&a, g_a);
    cudaGetSymbolAddress((void**)&q, g_q);
    cudaGetSymbolAddress((void**)&k, g_k);
    cudaGetSymbolAddress((void**)&v, g_v);
    cudaGetSymbolAddress((void**)&o, g_o);
    cudaGetSymbolAddress((void**)&m, g_m);
    cudaGetSymbolAddress((void**)&part, g_part);
    cudaGetSymbolAddress((void**)&whp, g_whp);
    cudaGetSymbolAddress((void**)&wq, g_wq);
    cudaGetSymbolAddress((void**)&wk, g_wk);
    cudaGetSymbolAddress((void**)&wv, g_wv);
    cudaGetSymbolAddress((void**)&wp, g_wp);
    cudaGetSymbolAddress((void**)&w1, g_w1);
    cudaGetSymbolAddress((void**)&w2, g_w2);

    cudaFuncSetAttribute(attn_kernel, cudaFuncAttributeMaxDynamicSharedMemorySize, ATT_SMEM);
    cudaFuncSetAttribute(qkv_kernel, cudaFuncAttributeMaxDynamicSharedMemorySize, GEMM_SMEM);
    cudaFuncSetAttribute(gemm_kernel<true, false, false, false, true, false>,
                         cudaFuncAttributeMaxDynamicSharedMemorySize, GEMM_SMEM);   // FF1
    cudaFuncSetAttribute(gemm_kernel<false, false, false, false, false, false>,
                         cudaFuncAttributeMaxDynamicSharedMemorySize, GEMM_SMEM);   // head
    cudaFuncSetAttribute(gemm_kernel<false, false, false, false, false, true>,
                         cudaFuncAttributeMaxDynamicSharedMemorySize, GEMM_SMEM);   // split-K

    // one-time weight packing (fp32 -> half2 along K)
    {
        int nH = N_LAYERS * N_HEADS * (D_MODEL / 2) * 16;     // headed qkv words/4
        pack_headed_kernel<<<(nH + 255) / 256, 256>>>(Wq, wq, N_LAYERS * N_HEADS, D_MODEL);
        pack_headed_kernel<<<(nH + 255) / 256, 256>>>(Wk, wk, N_LAYERS * N_HEADS, D_MODEL);
        pack_headed_kernel<<<(nH + 255) / 256, 256>>>(Wv, wv, N_LAYERS * N_HEADS, D_MODEL);
        int nP = (N_LAYERS * D_MODEL / 2) * (D_MODEL / 4);
        pack_kernel<<<(nP + 255) / 256, 256>>>(Wp, wp, N_LAYERS * D_MODEL / 2, D_MODEL / 4);
        int n1 = (N_LAYERS * D_MODEL / 2) * (D_FF / 4);
        pack_kernel<<<(n1 + 255) / 256, 256>>>(W1, w1, N_LAYERS * D_MODEL / 2, D_FF / 4);
        int n2 = (N_LAYERS * D_FF / 2) * (D_MODEL / 4);
        pack_kernel<<<(n2 + 255) / 256, 256>>>(W2, w2, N_LAYERS * D_FF / 2, D_MODEL / 4);
        pad_wh_kernel<<<dim3((VOCAB_P + 255) / 256, D_MODEL / 2), 256>>>(Wh, whp);
    }

    embed_kernel<<<ROWS, 256>>>(x, wte, wpe, h);

    dim3 gQKV(D_MODEL / 256, ROWS / 128, 3);          // (3, 32, 3)
    dim3 gSplit(D_MODEL / 256, ROWS / 128, 3);        // (3, 32, 3) split-K
    dim3 gFF1(D_FF / 256, ROWS / 128);                // (12, 32)
    dim3 gHead(VOCAB_P / 256, ROWS / 128);            // (197, 32)
    dim3 gAttn(SEQ / 128, N_HEADS, BATCH);            // (8, 12, 4)

    // layer 0 ln1
    ln_kernel<false><<<ROWS, 256>>>(h, ln1_w, ln1_b, nullptr, nullptr, a);

    const unsigned* aU = (const unsigned*)a;
    const unsigned* oU = (const unsigned*)o;
    const unsigned* mU = (const unsigned*)m;

    for (int l = 0; l < N_LAYERS; l++) {
        const unsigned* wq_l = wq + (size_t)l * WSZ / 2;
        const unsigned* wk_l = wk + (size_t)l * WSZ / 2;
        const unsigned* wv_l = wv + (size_t)l * WSZ / 2;
        const unsigned* wp_l = wp + (size_t)l * WSZ / 2;
        const unsigned* w1_l = w1 + (size_t)l * WSZ * 2;
        const unsigned* w2_l = w2 + (size_t)l * WSZ * 2;

        qkv_kernel<<<gQKV, 256, GEMM_SMEM>>>(aU, wq_l, wk_l, wv_l,
                                             bq + l * D_MODEL, bk + l * D_MODEL, bv + l * D_MODEL,
                                             q, k, v);

        attn_kernel<<<gAttn, 256, ATT_SMEM>>>(q, k, v, o);

        // proj: split-K x3 (K=768 -> 256 each), fused reduce + ln2∘lnfc
        gemm_kernel<false, false, false, false, false, true><<<gSplit, 256, GEMM_SMEM>>>(
            oU, wp_l, nullptr, nullptr, part, ROWS, D_MODEL, D_MODEL, D_MODEL, 256);
        lnred_kernel<true><<<ROWS, 256>>>(part, bp + l * D_MODEL, h,
                                          ln2_w + l * D_MODEL, ln2_b + l * D_MODEL,
                                          lnfc_w + l * D_MODEL, lnfc_b + l * D_MODEL, a);

        gemm_kernel<true, false, false, false, true, false><<<gFF1, 256, GEMM_SMEM>>>(
            aU, w1_l, b1 + l * D_FF, nullptr, m, ROWS, D_FF, D_MODEL, D_FF, D_MODEL);

        // FF2: split-K x3 (K=3072 -> 1024 each), fused reduce + next ln1 (or lnf)
        gemm_kernel<false, false, false, false, false, true><<<gSplit, 256, GEMM_SMEM>>>(
            mU, w2_l, nullptr, nullptr, part, ROWS, D_MODEL, D_FF, D_MODEL, 1024);
        if (l + 1 < N_LAYERS) {
            lnred_kernel<false><<<ROWS, 256>>>(part, b2 + l * D_MODEL, h,
                                               ln1_w + (l + 1) * D_MODEL,
                                               ln1_b + (l + 1) * D_MODEL,
                                               nullptr, nullptr, a);
        } else {
            lnred_kernel<false><<<ROWS, 256>>>(part, b2 + l * D_MODEL, h,
                                               lnf_w, lnf_b, nullptr, nullptr, a);
        }
    }

    gemm_kernel<false, false, false, false, false, false><<<gHead, 256, GEMM_SMEM>>>(
        aU, whp, bh, nullptr, out, ROWS, VOCAB_P, D_MODEL, VOCAB, D_MODEL);
}